// round 1
// baseline (speedup 1.0000x reference)
#include <cuda_runtime.h>
#include <cuda_bf16.h>
#include <math.h>

// Problem constants
constexpr int S_ = 256;
constexpr int Bb = 32;
constexpr int Hh = 512;
constexpr int Pp = 2048;
constexpr int Tt = Pp + S_;     // 2304
constexpr int Mm = Bb * S_;     // 8192
constexpr int Ff = 4 * Hh;      // 2048

constexpr float SCALE = 0.044194173824159223f;  // 1/sqrt(512)
constexpr float NEG_BIG = -1.0e30f;

// Scratch (device globals: allocation-free per harness rules)
__device__ float g_q[(size_t)Mm * Hh];
__device__ float g_k[(size_t)Mm * Hh];
__device__ float g_v[(size_t)Mm * Hh];
__device__ float g_sc[(size_t)Mm * Tt];     // scores -> probs (75.5 MB)
__device__ float g_at[(size_t)Mm * Hh];
__device__ float g_h1[(size_t)Mm * Hh];
__device__ float g_act[(size_t)Mm * Ff];    // 64 MB

// hidden is [S, B, H]; logical row m = b*S + s maps to hidden[(s*B + b)*H]
__device__ __forceinline__ size_t hid_off(int m) {
    int b = m >> 8;         // / S_
    int s = m & (S_ - 1);
    return ((size_t)s * Bb + b) * Hh;
}

// ---------------------------------------------------------------------------
// Generic GEMM: C[M,N] = A[M,K] @ W[K,N] + bias (+ epilogue)
// 128x128 tile, BK=16, 256 threads, 8x8 per thread, double-buffered smem.
// ---------------------------------------------------------------------------
#define BM 128
#define BN 128
#define BK 16

enum { E_BIAS = 0, E_GELU = 1, E_RES_HID = 2, E_RES_TRANS = 3 };

template<bool AHID, int EPI>
__global__ __launch_bounds__(256)
void gemm_kernel(const float* __restrict__ A, const float* __restrict__ W,
                 const float* __restrict__ bias, const float* __restrict__ R,
                 float* __restrict__ C, int K, int N)
{
    __shared__ float As[2][BK][BM];
    __shared__ float Bs[2][BK][BN];

    const int tid = threadIdx.x;
    const int m0 = blockIdx.y * BM;
    const int n0 = blockIdx.x * BN;
    const int tm = tid >> 4;     // 0..15
    const int tn = tid & 15;     // 0..15

    float acc[8][8];
    #pragma unroll
    for (int i = 0; i < 8; i++)
        #pragma unroll
        for (int j = 0; j < 8; j++) acc[i][j] = 0.f;

    const int KT = K / BK;

    auto loadA = [&](int kt, int u) -> float4 {
        int idx = tid + (u << 8);
        int row = idx >> 2, c4 = idx & 3;
        const float* ap = AHID ? (A + hid_off(m0 + row))
                               : (A + (size_t)(m0 + row) * K);
        return *reinterpret_cast<const float4*>(ap + kt * BK + c4 * 4);
    };
    auto loadB = [&](int kt, int u) -> float4 {
        int idx = tid + (u << 8);
        int kk = idx >> 5, n4 = idx & 31;
        return *reinterpret_cast<const float4*>(W + (size_t)(kt * BK + kk) * N + n0 + n4 * 4);
    };
    auto storeA = [&](int buf, int u, float4 val) {
        int idx = tid + (u << 8);
        int row = idx >> 2, c4 = idx & 3;
        As[buf][c4 * 4 + 0][row] = val.x;
        As[buf][c4 * 4 + 1][row] = val.y;
        As[buf][c4 * 4 + 2][row] = val.z;
        As[buf][c4 * 4 + 3][row] = val.w;
    };
    auto storeB = [&](int buf, int u, float4 val) {
        int idx = tid + (u << 8);
        int kk = idx >> 5, n4 = idx & 31;
        *reinterpret_cast<float4*>(&Bs[buf][kk][n4 * 4]) = val;
    };

    storeA(0, 0, loadA(0, 0)); storeA(0, 1, loadA(0, 1));
    storeB(0, 0, loadB(0, 0)); storeB(0, 1, loadB(0, 1));
    __syncthreads();

    for (int kt = 0; kt < KT; ++kt) {
        int buf = kt & 1;
        float4 ra0, ra1, rb0, rb1;
        bool more = (kt + 1 < KT);
        if (more) {
            ra0 = loadA(kt + 1, 0); ra1 = loadA(kt + 1, 1);
            rb0 = loadB(kt + 1, 0); rb1 = loadB(kt + 1, 1);
        }
        #pragma unroll
        for (int kk = 0; kk < BK; ++kk) {
            float a[8], b[8];
            *reinterpret_cast<float4*>(a)     = *reinterpret_cast<const float4*>(&As[buf][kk][tm * 8]);
            *reinterpret_cast<float4*>(a + 4) = *reinterpret_cast<const float4*>(&As[buf][kk][tm * 8 + 4]);
            *reinterpret_cast<float4*>(b)     = *reinterpret_cast<const float4*>(&Bs[buf][kk][tn * 8]);
            *reinterpret_cast<float4*>(b + 4) = *reinterpret_cast<const float4*>(&Bs[buf][kk][tn * 8 + 4]);
            #pragma unroll
            for (int i = 0; i < 8; i++)
                #pragma unroll
                for (int j = 0; j < 8; j++)
                    acc[i][j] = fmaf(a[i], b[j], acc[i][j]);
        }
        if (more) {
            storeA(buf ^ 1, 0, ra0); storeA(buf ^ 1, 1, ra1);
            storeB(buf ^ 1, 0, rb0); storeB(buf ^ 1, 1, rb1);
        }
        __syncthreads();
    }

    float bv[8];
    #pragma unroll
    for (int j = 0; j < 8; j++) bv[j] = bias[n0 + tn * 8 + j];

    #pragma unroll
    for (int i = 0; i < 8; i++) {
        int m = m0 + tm * 8 + i;
        int nb = n0 + tn * 8;
        #pragma unroll
        for (int j = 0; j < 8; j++) {
            float v = acc[i][j] + bv[j];
            if (EPI == E_GELU) {
                v = 0.5f * v * (1.f + erff(v * 0.70710678118654752f));
            } else if (EPI == E_RES_HID) {
                v += R[hid_off(m) + nb + j];
            } else if (EPI == E_RES_TRANS) {
                v += R[(size_t)m * N + nb + j];
            }
            if (EPI == E_RES_TRANS) {
                C[hid_off(m) + nb + j] = v;       // write back in [S,B,H] layout
            } else {
                C[(size_t)m * N + nb + j] = v;
            }
        }
    }
}

// ---------------------------------------------------------------------------
// Scores: per batch b, scores[b,s,j] = q[b,s,:] . K_all[b,j,:] * SCALE, masked
// K_all row j: j < P -> past_k[b,j,:], else k_new[b, j-P, :]
// ---------------------------------------------------------------------------
__global__ __launch_bounds__(256)
void scores_kernel(const float* __restrict__ q, const float* __restrict__ past_k,
                   const float* __restrict__ k_new, const int* __restrict__ past_lens,
                   float* __restrict__ scores)
{
    __shared__ float As[2][BK][BM];
    __shared__ float Bs[2][BK][BN];

    const int tid = threadIdx.x;
    const int b  = blockIdx.z;
    const int m0 = blockIdx.y * BM;    // query tile within S
    const int n0 = blockIdx.x * BN;    // key tile within T
    const int tm = tid >> 4;
    const int tn = tid & 15;

    const float* Aq = q + (size_t)b * S_ * Hh;

    float acc[8][8];
    #pragma unroll
    for (int i = 0; i < 8; i++)
        #pragma unroll
        for (int j = 0; j < 8; j++) acc[i][j] = 0.f;

    const int KT = Hh / BK;   // 32

    auto keyrow = [&](int j) -> const float* {
        return (j < Pp) ? (past_k + ((size_t)b * Pp + j) * Hh)
                        : (k_new + ((size_t)b * S_ + (j - Pp)) * Hh);
    };
    auto loadA = [&](int kt, int u) -> float4 {
        int idx = tid + (u << 8);
        int row = idx >> 2, c4 = idx & 3;
        return *reinterpret_cast<const float4*>(Aq + (size_t)(m0 + row) * Hh + kt * BK + c4 * 4);
    };
    auto loadB = [&](int kt, int u) -> float4 {
        int idx = tid + (u << 8);
        int row = idx >> 2, c4 = idx & 3;
        return *reinterpret_cast<const float4*>(keyrow(n0 + row) + kt * BK + c4 * 4);
    };
    auto storeA = [&](int buf, int u, float4 val) {
        int idx = tid + (u << 8);
        int row = idx >> 2, c4 = idx & 3;
        As[buf][c4 * 4 + 0][row] = val.x; As[buf][c4 * 4 + 1][row] = val.y;
        As[buf][c4 * 4 + 2][row] = val.z; As[buf][c4 * 4 + 3][row] = val.w;
    };
    auto storeB = [&](int buf, int u, float4 val) {
        int idx = tid + (u << 8);
        int row = idx >> 2, c4 = idx & 3;
        Bs[buf][c4 * 4 + 0][row] = val.x; Bs[buf][c4 * 4 + 1][row] = val.y;
        Bs[buf][c4 * 4 + 2][row] = val.z; Bs[buf][c4 * 4 + 3][row] = val.w;
    };

    storeA(0, 0, loadA(0, 0)); storeA(0, 1, loadA(0, 1));
    storeB(0, 0, loadB(0, 0)); storeB(0, 1, loadB(0, 1));
    __syncthreads();

    for (int kt = 0; kt < KT; ++kt) {
        int buf = kt & 1;
        float4 ra0, ra1, rb0, rb1;
        bool more = (kt + 1 < KT);
        if (more) {
            ra0 = loadA(kt + 1, 0); ra1 = loadA(kt + 1, 1);
            rb0 = loadB(kt + 1, 0); rb1 = loadB(kt + 1, 1);
        }
        #pragma unroll
        for (int kk = 0; kk < BK; ++kk) {
            float a[8], bb[8];
            *reinterpret_cast<float4*>(a)      = *reinterpret_cast<const float4*>(&As[buf][kk][tm * 8]);
            *reinterpret_cast<float4*>(a + 4)  = *reinterpret_cast<const float4*>(&As[buf][kk][tm * 8 + 4]);
            *reinterpret_cast<float4*>(bb)     = *reinterpret_cast<const float4*>(&Bs[buf][kk][tn * 8]);
            *reinterpret_cast<float4*>(bb + 4) = *reinterpret_cast<const float4*>(&Bs[buf][kk][tn * 8 + 4]);
            #pragma unroll
            for (int i = 0; i < 8; i++)
                #pragma unroll
                for (int j = 0; j < 8; j++)
                    acc[i][j] = fmaf(a[i], bb[j], acc[i][j]);
        }
        if (more) {
            storeA(buf ^ 1, 0, ra0); storeA(buf ^ 1, 1, ra1);
            storeB(buf ^ 1, 0, rb0); storeB(buf ^ 1, 1, rb1);
        }
        __syncthreads();
    }

    const int L = past_lens[b];
    #pragma unroll
    for (int i = 0; i < 8; i++) {
        int s = m0 + tm * 8 + i;   // query position
        #pragma unroll
        for (int j = 0; j < 8; j++) {
            int col = n0 + tn * 8 + j;
            bool valid = (col < Pp) ? (col < L) : ((col - Pp) <= s);
            float v = valid ? acc[i][j] * SCALE : NEG_BIG;
            scores[((size_t)b * S_ + s) * Tt + col] = v;
        }
    }
}

// ---------------------------------------------------------------------------
// Row softmax over T=2304 entries, one block per (b,s) row, values in regs.
// ---------------------------------------------------------------------------
__global__ __launch_bounds__(256)
void softmax_kernel(float* __restrict__ scores)
{
    __shared__ float red[8];
    const int tid = threadIdx.x;
    float* p = scores + (size_t)blockIdx.x * Tt;

    float v[9];
    float mx = NEG_BIG;
    #pragma unroll
    for (int i = 0; i < 9; i++) { v[i] = p[tid + (i << 8)]; mx = fmaxf(mx, v[i]); }
    #pragma unroll
    for (int o = 16; o > 0; o >>= 1) mx = fmaxf(mx, __shfl_xor_sync(0xffffffffu, mx, o));
    if ((tid & 31) == 0) red[tid >> 5] = mx;
    __syncthreads();
    float m2 = red[0];
    #pragma unroll
    for (int i = 1; i < 8; i++) m2 = fmaxf(m2, red[i]);

    float sum = 0.f;
    #pragma unroll
    for (int i = 0; i < 9; i++) { v[i] = __expf(v[i] - m2); sum += v[i]; }
    #pragma unroll
    for (int o = 16; o > 0; o >>= 1) sum += __shfl_xor_sync(0xffffffffu, sum, o);
    __syncthreads();
    if ((tid & 31) == 0) red[tid >> 5] = sum;
    __syncthreads();
    float s2 = 0.f;
    #pragma unroll
    for (int i = 0; i < 8; i++) s2 += red[i];

    float inv = 1.f / s2;
    #pragma unroll
    for (int i = 0; i < 9; i++) p[tid + (i << 8)] = v[i] * inv;
}

// ---------------------------------------------------------------------------
// PV: per batch b, attn[b,s,:] = probs[b,s,:] @ V_all[b,:,:]  (K = T = 2304)
// ---------------------------------------------------------------------------
__global__ __launch_bounds__(256)
void pv_kernel(const float* __restrict__ probs, const float* __restrict__ past_v,
               const float* __restrict__ v_new, float* __restrict__ attn)
{
    __shared__ float As[2][BK][BM];
    __shared__ float Bs[2][BK][BN];

    const int tid = threadIdx.x;
    const int b  = blockIdx.z;
    const int m0 = blockIdx.y * BM;   // query tile
    const int n0 = blockIdx.x * BN;   // h tile
    const int tm = tid >> 4;
    const int tn = tid & 15;

    const float* Ap = probs + (size_t)b * S_ * Tt;

    float acc[8][8];
    #pragma unroll
    for (int i = 0; i < 8; i++)
        #pragma unroll
        for (int j = 0; j < 8; j++) acc[i][j] = 0.f;

    const int KT = Tt / BK;   // 144

    auto vrow = [&](int kidx) -> const float* {
        return (kidx < Pp) ? (past_v + ((size_t)b * Pp + kidx) * Hh)
                           : (v_new + ((size_t)b * S_ + (kidx - Pp)) * Hh);
    };
    auto loadA = [&](int kt, int u) -> float4 {
        int idx = tid + (u << 8);
        int row = idx >> 2, c4 = idx & 3;
        return *reinterpret_cast<const float4*>(Ap + (size_t)(m0 + row) * Tt + kt * BK + c4 * 4);
    };
    auto loadB = [&](int kt, int u) -> float4 {
        int idx = tid + (u << 8);
        int kk = idx >> 5, n4 = idx & 31;
        return *reinterpret_cast<const float4*>(vrow(kt * BK + kk) + n0 + n4 * 4);
    };
    auto storeA = [&](int buf, int u, float4 val) {
        int idx = tid + (u << 8);
        int row = idx >> 2, c4 = idx & 3;
        As[buf][c4 * 4 + 0][row] = val.x; As[buf][c4 * 4 + 1][row] = val.y;
        As[buf][c4 * 4 + 2][row] = val.z; As[buf][c4 * 4 + 3][row] = val.w;
    };
    auto storeB = [&](int buf, int u, float4 val) {
        int idx = tid + (u << 8);
        int kk = idx >> 5, n4 = idx & 31;
        *reinterpret_cast<float4*>(&Bs[buf][kk][n4 * 4]) = val;
    };

    storeA(0, 0, loadA(0, 0)); storeA(0, 1, loadA(0, 1));
    storeB(0, 0, loadB(0, 0)); storeB(0, 1, loadB(0, 1));
    __syncthreads();

    for (int kt = 0; kt < KT; ++kt) {
        int buf = kt & 1;
        float4 ra0, ra1, rb0, rb1;
        bool more = (kt + 1 < KT);
        if (more) {
            ra0 = loadA(kt + 1, 0); ra1 = loadA(kt + 1, 1);
            rb0 = loadB(kt + 1, 0); rb1 = loadB(kt + 1, 1);
        }
        #pragma unroll
        for (int kk = 0; kk < BK; ++kk) {
            float a[8], bb[8];
            *reinterpret_cast<float4*>(a)      = *reinterpret_cast<const float4*>(&As[buf][kk][tm * 8]);
            *reinterpret_cast<float4*>(a + 4)  = *reinterpret_cast<const float4*>(&As[buf][kk][tm * 8 + 4]);
            *reinterpret_cast<float4*>(bb)     = *reinterpret_cast<const float4*>(&Bs[buf][kk][tn * 8]);
            *reinterpret_cast<float4*>(bb + 4) = *reinterpret_cast<const float4*>(&Bs[buf][kk][tn * 8 + 4]);
            #pragma unroll
            for (int i = 0; i < 8; i++)
                #pragma unroll
                for (int j = 0; j < 8; j++)
                    acc[i][j] = fmaf(a[i], bb[j], acc[i][j]);
        }
        if (more) {
            storeA(buf ^ 1, 0, ra0); storeA(buf ^ 1, 1, ra1);
            storeB(buf ^ 1, 0, rb0); storeB(buf ^ 1, 1, rb1);
        }
        __syncthreads();
    }

    #pragma unroll
    for (int i = 0; i < 8; i++) {
        int s = m0 + tm * 8 + i;
        #pragma unroll
        for (int j = 0; j < 8; j++) {
            attn[((size_t)b * S_ + s) * Hh + n0 + tn * 8 + j] = acc[i][j];
        }
    }
}

// ---------------------------------------------------------------------------
// Launch
// ---------------------------------------------------------------------------
extern "C" void kernel_launch(void* const* d_in, const int* in_sizes, int n_in,
                              void* d_out, int out_size)
{
    const float* hidden    = (const float*)d_in[0];
    const float* past_k    = (const float*)d_in[1];
    const float* past_v    = (const float*)d_in[2];
    const int*   past_lens = (const int*)  d_in[3];
    const float* Wq = (const float*)d_in[4];  const float* bq = (const float*)d_in[5];
    const float* Wk = (const float*)d_in[6];  const float* bk = (const float*)d_in[7];
    const float* Wv = (const float*)d_in[8];  const float* bv = (const float*)d_in[9];
    const float* Wo = (const float*)d_in[10]; const float* bo = (const float*)d_in[11];
    const float* W1 = (const float*)d_in[12]; const float* b1 = (const float*)d_in[13];
    const float* W2 = (const float*)d_in[14]; const float* b2 = (const float*)d_in[15];
    float* out = (float*)d_out;

    float *q, *k, *v, *sc, *at, *h1, *act;
    cudaGetSymbolAddress((void**)&q,   g_q);
    cudaGetSymbolAddress((void**)&k,   g_k);
    cudaGetSymbolAddress((void**)&v,   g_v);
    cudaGetSymbolAddress((void**)&sc,  g_sc);
    cudaGetSymbolAddress((void**)&at,  g_at);
    cudaGetSymbolAddress((void**)&h1,  g_h1);
    cudaGetSymbolAddress((void**)&act, g_act);

    dim3 blk(256);

    // QKV projections: [8192,512] = hidden(mapped) @ W + b
    dim3 gProj(Hh / BN, Mm / BM);
    gemm_kernel<true, E_BIAS><<<gProj, blk>>>(hidden, Wq, bq, nullptr, q, Hh, Hh);
    gemm_kernel<true, E_BIAS><<<gProj, blk>>>(hidden, Wk, bk, nullptr, k, Hh, Hh);
    gemm_kernel<true, E_BIAS><<<gProj, blk>>>(hidden, Wv, bv, nullptr, v, Hh, Hh);

    // Masked scores + softmax + PV
    scores_kernel<<<dim3(Tt / BN, S_ / BM, Bb), blk>>>(q, past_k, k, past_lens, sc);
    softmax_kernel<<<Mm, blk>>>(sc);
    pv_kernel<<<dim3(Hh / BN, S_ / BM, Bb), blk>>>(sc, past_v, v, at);

    // Output projection + residual (residual read from hidden with mapping)
    gemm_kernel<false, E_RES_HID><<<gProj, blk>>>(at, Wo, bo, hidden, h1, Hh, Hh);

    // FFN
    gemm_kernel<false, E_GELU><<<dim3(Ff / BN, Mm / BM), blk>>>(h1, W1, b1, nullptr, act, Hh, Ff);
    gemm_kernel<false, E_RES_TRANS><<<gProj, blk>>>(act, W2, b2, h1, out, Ff, Hh);
}

// round 2
// speedup vs baseline: 2.8599x; 2.8599x over previous
#include <cuda_runtime.h>
#include <cuda_bf16.h>
#include <math.h>
#include <stdint.h>

// Problem constants
constexpr int S_ = 256;
constexpr int Bb = 32;
constexpr int Hh = 512;
constexpr int Pp = 2048;
constexpr int Tt = Pp + S_;     // 2304
constexpr int Mm = Bb * S_;     // 8192
constexpr int Ff = 4 * Hh;      // 2048

constexpr float SCALE = 0.044194173824159223f;  // 1/sqrt(512)
constexpr float NEG_BIG = -1.0e30f;

// Scratch
__device__ float g_q[(size_t)Mm * Hh];
__device__ float g_k[(size_t)Mm * Hh];
__device__ float g_v[(size_t)Mm * Hh];
__device__ float g_sc[(size_t)Mm * Tt];
__device__ float g_at[(size_t)Mm * Hh];
__device__ float g_h1[(size_t)Mm * Hh];
__device__ float g_act[(size_t)Mm * Ff];

// hidden is [S, B, H]; logical row m = b*S + s maps to hidden[(s*B + b)*H]
__device__ __forceinline__ size_t hid_off(int m) {
    int b = m >> 8;
    int s = m & (S_ - 1);
    return ((size_t)s * Bb + b) * Hh;
}

__device__ __forceinline__ uint32_t f2tf(float x) {
    uint32_t u;
    asm("cvt.rna.tf32.f32 %0, %1;" : "=r"(u) : "f"(x));
    return u;
}

__device__ __forceinline__ void mma8(float* d, const uint32_t* a, const uint32_t* b) {
    asm volatile(
        "mma.sync.aligned.m16n8k8.row.col.f32.tf32.tf32.f32 "
        "{%0,%1,%2,%3},{%4,%5,%6,%7},{%8,%9},{%0,%1,%2,%3};"
        : "+f"(d[0]), "+f"(d[1]), "+f"(d[2]), "+f"(d[3])
        : "r"(a[0]), "r"(a[1]), "r"(a[2]), "r"(a[3]), "r"(b[0]), "r"(b[1]));
}

__device__ __forceinline__ void cvt_store4(uint32_t* dst, float4 v) {
    uint4 u;
    u.x = f2tf(v.x); u.y = f2tf(v.y); u.z = f2tf(v.z); u.w = f2tf(v.w);
    *reinterpret_cast<uint4*>(dst) = u;
}

#define BM 128
#define BN 128
#define BK 16
#define AKP 20     // A smem row stride (k-dim padded)
#define BNP 136    // B smem row stride (n-dim padded)

enum { E_BIAS = 0, E_GELU = 1, E_RES_HID = 2, E_RES_TRANS = 3 };

// ---------------------------------------------------------------------------
// Standard GEMM (tensor-core tf32): C[M,N] = A[M,K] @ W[K,N] + bias (+ epi)
// As: [m][k] pad-4 (direct float4 from row-major A). Bs: [k][n] pad-8.
// ---------------------------------------------------------------------------
template<bool AHID, int EPI>
__global__ __launch_bounds__(256)
void gemm_tc(const float* __restrict__ A, const float* __restrict__ W,
             const float* __restrict__ bias, const float* __restrict__ R,
             float* __restrict__ C, int K, int N)
{
    __shared__ uint32_t As[2][BM][AKP];
    __shared__ uint32_t Bs[2][BK][BNP];

    const int tid  = threadIdx.x;
    const int lane = tid & 31;
    const int warp = tid >> 5;
    const int wm   = warp & 3;       // 0..3 -> m offset wm*32
    const int wn   = warp >> 2;      // 0..1 -> n offset wn*64
    const int lr   = lane >> 2;      // 0..7
    const int lc   = lane & 3;       // 0..3
    const int m0   = blockIdx.y * BM;
    const int n0   = blockIdx.x * BN;

    float acc[2][8][4];
    #pragma unroll
    for (int i = 0; i < 2; i++)
        #pragma unroll
        for (int j = 0; j < 8; j++)
            #pragma unroll
            for (int t = 0; t < 4; t++) acc[i][j][t] = 0.f;

    const int KT = K / BK;

    auto loadA = [&](int kt, int u) -> float4 {
        int idx = tid + (u << 8);
        int m = idx >> 2, k4 = idx & 3;
        const float* ap = AHID ? (A + hid_off(m0 + m)) : (A + (size_t)(m0 + m) * K);
        return *reinterpret_cast<const float4*>(ap + kt * BK + k4 * 4);
    };
    auto loadB = [&](int kt, int u) -> float4 {
        int idx = tid + (u << 8);
        int k = idx >> 5, n4 = idx & 31;
        return *reinterpret_cast<const float4*>(W + (size_t)(kt * BK + k) * N + n0 + n4 * 4);
    };
    auto storeA = [&](int buf, int u, float4 v) {
        int idx = tid + (u << 8);
        int m = idx >> 2, k4 = idx & 3;
        cvt_store4(&As[buf][m][k4 * 4], v);
    };
    auto storeB = [&](int buf, int u, float4 v) {
        int idx = tid + (u << 8);
        int k = idx >> 5, n4 = idx & 31;
        cvt_store4(&Bs[buf][k][n4 * 4], v);
    };

    storeA(0, 0, loadA(0, 0)); storeA(0, 1, loadA(0, 1));
    storeB(0, 0, loadB(0, 0)); storeB(0, 1, loadB(0, 1));
    __syncthreads();

    for (int kt = 0; kt < KT; ++kt) {
        int buf = kt & 1;
        float4 ra0, ra1, rb0, rb1;
        bool more = (kt + 1 < KT);
        if (more) {
            ra0 = loadA(kt + 1, 0); ra1 = loadA(kt + 1, 1);
            rb0 = loadB(kt + 1, 0); rb1 = loadB(kt + 1, 1);
        }
        #pragma unroll
        for (int ks = 0; ks < 2; ks++) {
            const int kk = ks * 8 + lc;
            uint32_t af[2][4];
            #pragma unroll
            for (int mt = 0; mt < 2; mt++) {
                int r = wm * 32 + mt * 16 + lr;
                af[mt][0] = As[buf][r][kk];
                af[mt][1] = As[buf][r + 8][kk];
                af[mt][2] = As[buf][r][kk + 4];
                af[mt][3] = As[buf][r + 8][kk + 4];
            }
            uint32_t bf[8][2];
            #pragma unroll
            for (int nt = 0; nt < 8; nt++) {
                int cc = wn * 64 + nt * 8 + lr;
                bf[nt][0] = Bs[buf][kk][cc];
                bf[nt][1] = Bs[buf][kk + 4][cc];
            }
            #pragma unroll
            for (int mt = 0; mt < 2; mt++)
                #pragma unroll
                for (int nt = 0; nt < 8; nt++)
                    mma8(acc[mt][nt], af[mt], bf[nt]);
        }
        if (more) {
            storeA(buf ^ 1, 0, ra0); storeA(buf ^ 1, 1, ra1);
            storeB(buf ^ 1, 0, rb0); storeB(buf ^ 1, 1, rb1);
        }
        __syncthreads();
    }

    // Epilogue
    #pragma unroll
    for (int nt = 0; nt < 8; nt++) {
        int c = n0 + wn * 64 + nt * 8 + lc * 2;
        float bv0 = bias[c], bv1 = bias[c + 1];
        #pragma unroll
        for (int mt = 0; mt < 2; mt++) {
            int r0 = m0 + wm * 32 + mt * 16 + lr;
            int r1 = r0 + 8;
            float v00 = acc[mt][nt][0] + bv0;
            float v01 = acc[mt][nt][1] + bv1;
            float v10 = acc[mt][nt][2] + bv0;
            float v11 = acc[mt][nt][3] + bv1;
            if (EPI == E_GELU) {
                v00 = 0.5f * v00 * (1.f + erff(v00 * 0.70710678118654752f));
                v01 = 0.5f * v01 * (1.f + erff(v01 * 0.70710678118654752f));
                v10 = 0.5f * v10 * (1.f + erff(v10 * 0.70710678118654752f));
                v11 = 0.5f * v11 * (1.f + erff(v11 * 0.70710678118654752f));
            } else if (EPI == E_RES_HID) {
                const float* rp0 = R + hid_off(r0) + c;
                const float* rp1 = R + hid_off(r1) + c;
                v00 += rp0[0]; v01 += rp0[1];
                v10 += rp1[0]; v11 += rp1[1];
            } else if (EPI == E_RES_TRANS) {
                const float* rp0 = R + (size_t)r0 * N + c;
                const float* rp1 = R + (size_t)r1 * N + c;
                v00 += rp0[0]; v01 += rp0[1];
                v10 += rp1[0]; v11 += rp1[1];
            }
            if (EPI == E_RES_TRANS) {
                *reinterpret_cast<float2*>(C + hid_off(r0) + c) = make_float2(v00, v01);
                *reinterpret_cast<float2*>(C + hid_off(r1) + c) = make_float2(v10, v11);
            } else {
                *reinterpret_cast<float2*>(C + (size_t)r0 * N + c) = make_float2(v00, v01);
                *reinterpret_cast<float2*>(C + (size_t)r1 * N + c) = make_float2(v10, v11);
            }
        }
    }
}

// ---------------------------------------------------------------------------
// Scores (tensor-core): scores[b,s,j] = q[b,s,:] . K_all[b,j,:] * SCALE masked
// Bs stored n-major [n][k] pad-4 (keys are k-contiguous in gmem).
// ---------------------------------------------------------------------------
__global__ __launch_bounds__(256)
void scores_tc(const float* __restrict__ q, const float* __restrict__ past_k,
               const float* __restrict__ k_new, const int* __restrict__ past_lens,
               float* __restrict__ scores)
{
    __shared__ uint32_t As[2][BM][AKP];
    __shared__ uint32_t Bs[2][BN][AKP];

    const int tid  = threadIdx.x;
    const int lane = tid & 31;
    const int warp = tid >> 5;
    const int wm   = warp & 3;
    const int wn   = warp >> 2;
    const int lr   = lane >> 2;
    const int lc   = lane & 3;
    const int b    = blockIdx.z;
    const int m0   = blockIdx.y * BM;
    const int n0   = blockIdx.x * BN;

    const float* Aq = q + (size_t)b * S_ * Hh;

    float acc[2][8][4];
    #pragma unroll
    for (int i = 0; i < 2; i++)
        #pragma unroll
        for (int j = 0; j < 8; j++)
            #pragma unroll
            for (int t = 0; t < 4; t++) acc[i][j][t] = 0.f;

    const int KT = Hh / BK;   // 32

    auto keyrow = [&](int j) -> const float* {
        return (j < Pp) ? (past_k + ((size_t)b * Pp + j) * Hh)
                        : (k_new + ((size_t)b * S_ + (j - Pp)) * Hh);
    };
    auto loadA = [&](int kt, int u) -> float4 {
        int idx = tid + (u << 8);
        int m = idx >> 2, k4 = idx & 3;
        return *reinterpret_cast<const float4*>(Aq + (size_t)(m0 + m) * Hh + kt * BK + k4 * 4);
    };
    auto loadB = [&](int kt, int u) -> float4 {
        int idx = tid + (u << 8);
        int n = idx >> 2, k4 = idx & 3;
        return *reinterpret_cast<const float4*>(keyrow(n0 + n) + kt * BK + k4 * 4);
    };
    auto storeA = [&](int buf, int u, float4 v) {
        int idx = tid + (u << 8);
        int m = idx >> 2, k4 = idx & 3;
        cvt_store4(&As[buf][m][k4 * 4], v);
    };
    auto storeB = [&](int buf, int u, float4 v) {
        int idx = tid + (u << 8);
        int n = idx >> 2, k4 = idx & 3;
        cvt_store4(&Bs[buf][n][k4 * 4], v);
    };

    storeA(0, 0, loadA(0, 0)); storeA(0, 1, loadA(0, 1));
    storeB(0, 0, loadB(0, 0)); storeB(0, 1, loadB(0, 1));
    __syncthreads();

    for (int kt = 0; kt < KT; ++kt) {
        int buf = kt & 1;
        float4 ra0, ra1, rb0, rb1;
        bool more = (kt + 1 < KT);
        if (more) {
            ra0 = loadA(kt + 1, 0); ra1 = loadA(kt + 1, 1);
            rb0 = loadB(kt + 1, 0); rb1 = loadB(kt + 1, 1);
        }
        #pragma unroll
        for (int ks = 0; ks < 2; ks++) {
            const int kk = ks * 8 + lc;
            uint32_t af[2][4];
            #pragma unroll
            for (int mt = 0; mt < 2; mt++) {
                int r = wm * 32 + mt * 16 + lr;
                af[mt][0] = As[buf][r][kk];
                af[mt][1] = As[buf][r + 8][kk];
                af[mt][2] = As[buf][r][kk + 4];
                af[mt][3] = As[buf][r + 8][kk + 4];
            }
            uint32_t bf[8][2];
            #pragma unroll
            for (int nt = 0; nt < 8; nt++) {
                int cc = wn * 64 + nt * 8 + lr;
                bf[nt][0] = Bs[buf][cc][kk];
                bf[nt][1] = Bs[buf][cc][kk + 4];
            }
            #pragma unroll
            for (int mt = 0; mt < 2; mt++)
                #pragma unroll
                for (int nt = 0; nt < 8; nt++)
                    mma8(acc[mt][nt], af[mt], bf[nt]);
        }
        if (more) {
            storeA(buf ^ 1, 0, ra0); storeA(buf ^ 1, 1, ra1);
            storeB(buf ^ 1, 0, rb0); storeB(buf ^ 1, 1, rb1);
        }
        __syncthreads();
    }

    const int L = past_lens[b];
    #pragma unroll
    for (int mt = 0; mt < 2; mt++) {
        #pragma unroll
        for (int nt = 0; nt < 8; nt++) {
            int c  = n0 + wn * 64 + nt * 8 + lc * 2;
            #pragma unroll
            for (int half = 0; half < 2; half++) {
                int s = m0 + wm * 32 + mt * 16 + lr + half * 8;
                float v0 = acc[mt][nt][half * 2 + 0];
                float v1 = acc[mt][nt][half * 2 + 1];
                bool ok0 = (c < Pp) ? (c < L) : ((c - Pp) <= s);
                int c1 = c + 1;
                bool ok1 = (c1 < Pp) ? (c1 < L) : ((c1 - Pp) <= s);
                float o0 = ok0 ? v0 * SCALE : NEG_BIG;
                float o1 = ok1 ? v1 * SCALE : NEG_BIG;
                *reinterpret_cast<float2*>(scores + ((size_t)b * S_ + s) * Tt + c) =
                    make_float2(o0, o1);
            }
        }
    }
}

// ---------------------------------------------------------------------------
// PV (tensor-core): attn[b,s,:] = probs[b,s,:] @ V_all[b,:,:]   K = T = 2304
// ---------------------------------------------------------------------------
__global__ __launch_bounds__(256)
void pv_tc(const float* __restrict__ probs, const float* __restrict__ past_v,
           const float* __restrict__ v_new, float* __restrict__ attn)
{
    __shared__ uint32_t As[2][BM][AKP];
    __shared__ uint32_t Bs[2][BK][BNP];

    const int tid  = threadIdx.x;
    const int lane = tid & 31;
    const int warp = tid >> 5;
    const int wm   = warp & 3;
    const int wn   = warp >> 2;
    const int lr   = lane >> 2;
    const int lc   = lane & 3;
    const int b    = blockIdx.z;
    const int m0   = blockIdx.y * BM;
    const int n0   = blockIdx.x * BN;

    const float* Ap = probs + (size_t)b * S_ * Tt;

    float acc[2][8][4];
    #pragma unroll
    for (int i = 0; i < 2; i++)
        #pragma unroll
        for (int j = 0; j < 8; j++)
            #pragma unroll
            for (int t = 0; t < 4; t++) acc[i][j][t] = 0.f;

    const int KT = Tt / BK;   // 144

    auto vrow = [&](int kidx) -> const float* {
        return (kidx < Pp) ? (past_v + ((size_t)b * Pp + kidx) * Hh)
                           : (v_new + ((size_t)b * S_ + (kidx - Pp)) * Hh);
    };
    auto loadA = [&](int kt, int u) -> float4 {
        int idx = tid + (u << 8);
        int m = idx >> 2, k4 = idx & 3;
        return *reinterpret_cast<const float4*>(Ap + (size_t)(m0 + m) * Tt + kt * BK + k4 * 4);
    };
    auto loadB = [&](int kt, int u) -> float4 {
        int idx = tid + (u << 8);
        int k = idx >> 5, n4 = idx & 31;
        return *reinterpret_cast<const float4*>(vrow(kt * BK + k) + n0 + n4 * 4);
    };
    auto storeA = [&](int buf, int u, float4 v) {
        int idx = tid + (u << 8);
        int m = idx >> 2, k4 = idx & 3;
        cvt_store4(&As[buf][m][k4 * 4], v);
    };
    auto storeB = [&](int buf, int u, float4 v) {
        int idx = tid + (u << 8);
        int k = idx >> 5, n4 = idx & 31;
        cvt_store4(&Bs[buf][k][n4 * 4], v);
    };

    storeA(0, 0, loadA(0, 0)); storeA(0, 1, loadA(0, 1));
    storeB(0, 0, loadB(0, 0)); storeB(0, 1, loadB(0, 1));
    __syncthreads();

    for (int kt = 0; kt < KT; ++kt) {
        int buf = kt & 1;
        float4 ra0, ra1, rb0, rb1;
        bool more = (kt + 1 < KT);
        if (more) {
            ra0 = loadA(kt + 1, 0); ra1 = loadA(kt + 1, 1);
            rb0 = loadB(kt + 1, 0); rb1 = loadB(kt + 1, 1);
        }
        #pragma unroll
        for (int ks = 0; ks < 2; ks++) {
            const int kk = ks * 8 + lc;
            uint32_t af[2][4];
            #pragma unroll
            for (int mt = 0; mt < 2; mt++) {
                int r = wm * 32 + mt * 16 + lr;
                af[mt][0] = As[buf][r][kk];
                af[mt][1] = As[buf][r + 8][kk];
                af[mt][2] = As[buf][r][kk + 4];
                af[mt][3] = As[buf][r + 8][kk + 4];
            }
            uint32_t bf[8][2];
            #pragma unroll
            for (int nt = 0; nt < 8; nt++) {
                int cc = wn * 64 + nt * 8 + lr;
                bf[nt][0] = Bs[buf][kk][cc];
                bf[nt][1] = Bs[buf][kk + 4][cc];
            }
            #pragma unroll
            for (int mt = 0; mt < 2; mt++)
                #pragma unroll
                for (int nt = 0; nt < 8; nt++)
                    mma8(acc[mt][nt], af[mt], bf[nt]);
        }
        if (more) {
            storeA(buf ^ 1, 0, ra0); storeA(buf ^ 1, 1, ra1);
            storeB(buf ^ 1, 0, rb0); storeB(buf ^ 1, 1, rb1);
        }
        __syncthreads();
    }

    #pragma unroll
    for (int mt = 0; mt < 2; mt++) {
        #pragma unroll
        for (int nt = 0; nt < 8; nt++) {
            int c = n0 + wn * 64 + nt * 8 + lc * 2;
            int r0 = m0 + wm * 32 + mt * 16 + lr;
            int r1 = r0 + 8;
            *reinterpret_cast<float2*>(attn + ((size_t)b * S_ + r0) * Hh + c) =
                make_float2(acc[mt][nt][0], acc[mt][nt][1]);
            *reinterpret_cast<float2*>(attn + ((size_t)b * S_ + r1) * Hh + c) =
                make_float2(acc[mt][nt][2], acc[mt][nt][3]);
        }
    }
}

// ---------------------------------------------------------------------------
// Row softmax over T=2304, one block per (b,s) row.
// ---------------------------------------------------------------------------
__global__ __launch_bounds__(256)
void softmax_kernel(float* __restrict__ scores)
{
    __shared__ float red[8];
    const int tid = threadIdx.x;
    float* p = scores + (size_t)blockIdx.x * Tt;

    float v[9];
    float mx = NEG_BIG;
    #pragma unroll
    for (int i = 0; i < 9; i++) { v[i] = p[tid + (i << 8)]; mx = fmaxf(mx, v[i]); }
    #pragma unroll
    for (int o = 16; o > 0; o >>= 1) mx = fmaxf(mx, __shfl_xor_sync(0xffffffffu, mx, o));
    if ((tid & 31) == 0) red[tid >> 5] = mx;
    __syncthreads();
    float m2 = red[0];
    #pragma unroll
    for (int i = 1; i < 8; i++) m2 = fmaxf(m2, red[i]);

    float sum = 0.f;
    #pragma unroll
    for (int i = 0; i < 9; i++) { v[i] = __expf(v[i] - m2); sum += v[i]; }
    #pragma unroll
    for (int o = 16; o > 0; o >>= 1) sum += __shfl_xor_sync(0xffffffffu, sum, o);
    __syncthreads();
    if ((tid & 31) == 0) red[tid >> 5] = sum;
    __syncthreads();
    float s2 = 0.f;
    #pragma unroll
    for (int i = 0; i < 8; i++) s2 += red[i];

    float inv = 1.f / s2;
    #pragma unroll
    for (int i = 0; i < 9; i++) p[tid + (i << 8)] = v[i] * inv;
}

// ---------------------------------------------------------------------------
// Launch
// ---------------------------------------------------------------------------
extern "C" void kernel_launch(void* const* d_in, const int* in_sizes, int n_in,
                              void* d_out, int out_size)
{
    const float* hidden    = (const float*)d_in[0];
    const float* past_k    = (const float*)d_in[1];
    const float* past_v    = (const float*)d_in[2];
    const int*   past_lens = (const int*)  d_in[3];
    const float* Wq = (const float*)d_in[4];  const float* bq = (const float*)d_in[5];
    const float* Wk = (const float*)d_in[6];  const float* bk = (const float*)d_in[7];
    const float* Wv = (const float*)d_in[8];  const float* bv = (const float*)d_in[9];
    const float* Wo = (const float*)d_in[10]; const float* bo = (const float*)d_in[11];
    const float* W1 = (const float*)d_in[12]; const float* b1 = (const float*)d_in[13];
    const float* W2 = (const float*)d_in[14]; const float* b2 = (const float*)d_in[15];
    float* out = (float*)d_out;

    float *q, *k, *v, *sc, *at, *h1, *act;
    cudaGetSymbolAddress((void**)&q,   g_q);
    cudaGetSymbolAddress((void**)&k,   g_k);
    cudaGetSymbolAddress((void**)&v,   g_v);
    cudaGetSymbolAddress((void**)&sc,  g_sc);
    cudaGetSymbolAddress((void**)&at,  g_at);
    cudaGetSymbolAddress((void**)&h1,  g_h1);
    cudaGetSymbolAddress((void**)&act, g_act);

    dim3 blk(256);
    dim3 gProj(Hh / BN, Mm / BM);   // (4, 64)

    // QKV projections
    gemm_tc<true, E_BIAS><<<gProj, blk>>>(hidden, Wq, bq, nullptr, q, Hh, Hh);
    gemm_tc<true, E_BIAS><<<gProj, blk>>>(hidden, Wk, bk, nullptr, k, Hh, Hh);
    gemm_tc<true, E_BIAS><<<gProj, blk>>>(hidden, Wv, bv, nullptr, v, Hh, Hh);

    // Attention
    scores_tc<<<dim3(Tt / BN, S_ / BM, Bb), blk>>>(q, past_k, k, past_lens, sc);
    softmax_kernel<<<Mm, blk>>>(sc);
    pv_tc<<<dim3(Hh / BN, S_ / BM, Bb), blk>>>(sc, past_v, v, at);

    // Output projection + residual
    gemm_tc<false, E_RES_HID><<<gProj, blk>>>(at, Wo, bo, hidden, h1, Hh, Hh);

    // FFN
    gemm_tc<false, E_GELU><<<dim3(Ff / BN, Mm / BM), blk>>>(h1, W1, b1, nullptr, act, Hh, Ff);
    gemm_tc<false, E_RES_TRANS><<<gProj, blk>>>(act, W2, b2, h1, out, Ff, Hh);
}

// round 3
// speedup vs baseline: 3.6994x; 1.2935x over previous
#include <cuda_runtime.h>
#include <cuda_bf16.h>
#include <math.h>
#include <stdint.h>

// Problem constants
constexpr int S_ = 256;
constexpr int Bb = 32;
constexpr int Hh = 512;
constexpr int Pp = 2048;
constexpr int Tt = Pp + S_;     // 2304
constexpr int Mm = Bb * S_;     // 8192
constexpr int Ff = 4 * Hh;      // 2048

constexpr float SCALE = 0.044194173824159223f;  // 1/sqrt(512)
constexpr float NEG_BIG = -1.0e30f;

// Scratch
__device__ float g_q[(size_t)Mm * Hh];
__device__ float g_k[(size_t)Mm * Hh];
__device__ float g_v[(size_t)Mm * Hh];
__device__ float g_sc[(size_t)Mm * Tt];
__device__ float g_at[(size_t)Mm * Hh];
__device__ float g_h1[(size_t)Mm * Hh];     // exact (residual)
__device__ float g_h1r[(size_t)Mm * Hh];    // rounded (FFN-A)
__device__ float g_act[(size_t)Mm * Ff];
// Pre-rounded inputs
__device__ float g_hr[(size_t)S_ * Bb * Hh];
__device__ float g_wq[Hh * Hh];
__device__ float g_wk[Hh * Hh];
__device__ float g_wv[Hh * Hh];
__device__ float g_wo[Hh * Hh];
__device__ float g_w1[Hh * Ff];
__device__ float g_w2[Ff * Hh];

// hidden is [S, B, H]; logical row m = b*S + s maps to hidden[(s*B + b)*H]
__device__ __forceinline__ size_t hid_off(int m) {
    int b = m >> 8;
    int s = m & (S_ - 1);
    return ((size_t)s * Bb + b) * Hh;
}

__device__ __forceinline__ float rnd_tf32(float x) {
    uint32_t u;
    asm("cvt.rna.tf32.f32 %0, %1;" : "=r"(u) : "f"(x));
    return __uint_as_float(u);
}

__device__ __forceinline__ void mma8(float* d, const uint32_t* a, const uint32_t* b) {
    asm volatile(
        "mma.sync.aligned.m16n8k8.row.col.f32.tf32.tf32.f32 "
        "{%0,%1,%2,%3},{%4,%5,%6,%7},{%8,%9},{%0,%1,%2,%3};"
        : "+f"(d[0]), "+f"(d[1]), "+f"(d[2]), "+f"(d[3])
        : "r"(a[0]), "r"(a[1]), "r"(a[2]), "r"(a[3]), "r"(b[0]), "r"(b[1]));
}

__device__ __forceinline__ void cp16(void* smem, const void* g) {
    uint32_t s = (uint32_t)__cvta_generic_to_shared(smem);
    asm volatile("cp.async.cg.shared.global [%0], [%1], 16;" :: "r"(s), "l"(g));
}
__device__ __forceinline__ void cp_commit() { asm volatile("cp.async.commit_group;"); }
template<int N>
__device__ __forceinline__ void cp_wait() { asm volatile("cp.async.wait_group %0;" :: "n"(N)); }

__device__ __forceinline__ uint32_t u32of(float f) { return __float_as_uint(f); }

#define BM 128
#define BN 128
#define BK 16
#define AKP 20     // [row][k] stride (k padded)
#define BNP 136    // [k][n] stride (n padded)
#define ST 4       // pipeline stages

enum { E_BIAS = 0, E_GELU = 1, E_RES_HID = 2, E_RES_TRANS = 3 };

constexpr int SMEM_GEMM   = ST * (BM * AKP + BK * BNP) * 4;   // 75776 B
constexpr int SMEM_SCORES = ST * (BM * AKP + BN * AKP) * 4;   // 81920 B

// ---------------------------------------------------------------------------
// Pre-round kernel (RNA to tf32, value kept in f32)
// ---------------------------------------------------------------------------
__global__ void round_copy(const float* __restrict__ s, float* __restrict__ d, int n4)
{
    int i = blockIdx.x * blockDim.x + threadIdx.x;
    if (i < n4) {
        float4 v = reinterpret_cast<const float4*>(s)[i];
        v.x = rnd_tf32(v.x); v.y = rnd_tf32(v.y);
        v.z = rnd_tf32(v.z); v.w = rnd_tf32(v.w);
        reinterpret_cast<float4*>(d)[i] = v;
    }
}

// ---------------------------------------------------------------------------
// Standard GEMM: C[M,N] = A[M,K] @ W[K,N] + bias (+ epilogue)
// cp.async 4-stage; As [m][k]+pad, Bs [k][n]+pad. A/W pre-rounded to tf32.
// ---------------------------------------------------------------------------
template<bool AHID, int EPI, bool ROUND>
__global__ __launch_bounds__(256, 2)
void gemm_tc(const float* __restrict__ A, const float* __restrict__ W,
             const float* __restrict__ bias, const float* __restrict__ R,
             float* __restrict__ C, float* __restrict__ C2, int K, int N)
{
    extern __shared__ float sm[];
    float* As = sm;                       // [ST][BM][AKP]
    float* Bs = sm + ST * BM * AKP;       // [ST][BK][BNP]

    const int tid  = threadIdx.x;
    const int lane = tid & 31;
    const int warp = tid >> 5;
    const int wm   = warp & 3;
    const int wn   = warp >> 2;
    const int lr   = lane >> 2;
    const int lc   = lane & 3;
    const int m0   = blockIdx.y * BM;
    const int n0   = blockIdx.x * BN;
    const int KT   = K / BK;

    auto issue = [&](int kt) {
        int st = kt % ST;
        float* Ad = As + st * BM * AKP;
        float* Bd = Bs + st * BK * BNP;
        #pragma unroll
        for (int u = 0; u < 2; u++) {
            int c = tid + (u << 8);
            int m = c >> 2, k4 = c & 3;
            const float* g = (AHID ? (A + hid_off(m0 + m)) : (A + (size_t)(m0 + m) * K))
                             + kt * BK + k4 * 4;
            cp16(Ad + m * AKP + k4 * 4, g);
        }
        #pragma unroll
        for (int u = 0; u < 2; u++) {
            int c = tid + (u << 8);
            int k = c >> 5, n4 = c & 31;
            cp16(Bd + k * BNP + n4 * 4, W + (size_t)(kt * BK + k) * N + n0 + n4 * 4);
        }
        cp_commit();
    };

    float acc[2][8][4];
    #pragma unroll
    for (int i = 0; i < 2; i++)
        #pragma unroll
        for (int j = 0; j < 8; j++)
            #pragma unroll
            for (int t = 0; t < 4; t++) acc[i][j][t] = 0.f;

    #pragma unroll
    for (int p = 0; p < ST - 1; p++) issue(p);

    for (int kt = 0; kt < KT; ++kt) {
        cp_wait<ST - 2>();
        __syncthreads();
        const float* Ab = As + (kt % ST) * BM * AKP;
        const float* Bbuf = Bs + (kt % ST) * BK * BNP;

        #pragma unroll
        for (int ks = 0; ks < 2; ks++) {
            const int kk = ks * 8 + lc;
            uint32_t af[2][4];
            #pragma unroll
            for (int mt = 0; mt < 2; mt++) {
                int r = wm * 32 + mt * 16 + lr;
                af[mt][0] = u32of(Ab[r * AKP + kk]);
                af[mt][1] = u32of(Ab[(r + 8) * AKP + kk]);
                af[mt][2] = u32of(Ab[r * AKP + kk + 4]);
                af[mt][3] = u32of(Ab[(r + 8) * AKP + kk + 4]);
            }
            uint32_t bf[8][2];
            #pragma unroll
            for (int nt = 0; nt < 8; nt++) {
                int cc = wn * 64 + nt * 8 + lr;
                bf[nt][0] = u32of(Bbuf[kk * BNP + cc]);
                bf[nt][1] = u32of(Bbuf[(kk + 4) * BNP + cc]);
            }
            #pragma unroll
            for (int mt = 0; mt < 2; mt++)
                #pragma unroll
                for (int nt = 0; nt < 8; nt++)
                    mma8(acc[mt][nt], af[mt], bf[nt]);
        }
        if (kt + ST - 1 < KT) issue(kt + ST - 1); else cp_commit();
    }

    // Epilogue
    #pragma unroll
    for (int nt = 0; nt < 8; nt++) {
        int c = n0 + wn * 64 + nt * 8 + lc * 2;
        float bv0 = bias[c], bv1 = bias[c + 1];
        #pragma unroll
        for (int mt = 0; mt < 2; mt++) {
            int r0 = m0 + wm * 32 + mt * 16 + lr;
            int r1 = r0 + 8;
            float v00 = acc[mt][nt][0] + bv0;
            float v01 = acc[mt][nt][1] + bv1;
            float v10 = acc[mt][nt][2] + bv0;
            float v11 = acc[mt][nt][3] + bv1;
            if (EPI == E_GELU) {
                v00 = 0.5f * v00 * (1.f + erff(v00 * 0.70710678118654752f));
                v01 = 0.5f * v01 * (1.f + erff(v01 * 0.70710678118654752f));
                v10 = 0.5f * v10 * (1.f + erff(v10 * 0.70710678118654752f));
                v11 = 0.5f * v11 * (1.f + erff(v11 * 0.70710678118654752f));
            } else if (EPI == E_RES_HID) {
                const float* rp0 = R + hid_off(r0) + c;
                const float* rp1 = R + hid_off(r1) + c;
                v00 += rp0[0]; v01 += rp0[1];
                v10 += rp1[0]; v11 += rp1[1];
            } else if (EPI == E_RES_TRANS) {
                const float* rp0 = R + (size_t)r0 * N + c;
                const float* rp1 = R + (size_t)r1 * N + c;
                v00 += rp0[0]; v01 += rp0[1];
                v10 += rp1[0]; v11 += rp1[1];
            }
            if (EPI == E_RES_HID) {
                // exact h1 for residual, rounded copy for FFN-A
                *reinterpret_cast<float2*>(C  + (size_t)r0 * N + c) = make_float2(v00, v01);
                *reinterpret_cast<float2*>(C  + (size_t)r1 * N + c) = make_float2(v10, v11);
                *reinterpret_cast<float2*>(C2 + (size_t)r0 * N + c) =
                    make_float2(rnd_tf32(v00), rnd_tf32(v01));
                *reinterpret_cast<float2*>(C2 + (size_t)r1 * N + c) =
                    make_float2(rnd_tf32(v10), rnd_tf32(v11));
            } else {
                if (ROUND) {
                    v00 = rnd_tf32(v00); v01 = rnd_tf32(v01);
                    v10 = rnd_tf32(v10); v11 = rnd_tf32(v11);
                }
                if (EPI == E_RES_TRANS) {
                    *reinterpret_cast<float2*>(C + hid_off(r0) + c) = make_float2(v00, v01);
                    *reinterpret_cast<float2*>(C + hid_off(r1) + c) = make_float2(v10, v11);
                } else {
                    *reinterpret_cast<float2*>(C + (size_t)r0 * N + c) = make_float2(v00, v01);
                    *reinterpret_cast<float2*>(C + (size_t)r1 * N + c) = make_float2(v10, v11);
                }
            }
        }
    }
}

// ---------------------------------------------------------------------------
// Scores: scores[b,s,j] = q[b,s,:] . K_all[b,j,:] * SCALE, masked.
// Bs n-major [n][k]+pad (keys k-contiguous in gmem -> cp.async friendly).
// ---------------------------------------------------------------------------
__global__ __launch_bounds__(256, 2)
void scores_tc(const float* __restrict__ q, const float* __restrict__ past_k,
               const float* __restrict__ k_new, const int* __restrict__ past_lens,
               float* __restrict__ scores)
{
    extern __shared__ float sm[];
    float* As = sm;                       // [ST][BM][AKP]
    float* Bs = sm + ST * BM * AKP;       // [ST][BN][AKP]

    const int tid  = threadIdx.x;
    const int lane = tid & 31;
    const int warp = tid >> 5;
    const int wm   = warp & 3;
    const int wn   = warp >> 2;
    const int lr   = lane >> 2;
    const int lc   = lane & 3;
    const int b    = blockIdx.z;
    const int m0   = blockIdx.y * BM;
    const int n0   = blockIdx.x * BN;
    const int KT   = Hh / BK;   // 32

    const float* Aq = q + (size_t)b * S_ * Hh;

    auto keyrow = [&](int j) -> const float* {
        return (j < Pp) ? (past_k + ((size_t)b * Pp + j) * Hh)
                        : (k_new + ((size_t)b * S_ + (j - Pp)) * Hh);
    };
    auto issue = [&](int kt) {
        int st = kt % ST;
        float* Ad = As + st * BM * AKP;
        float* Bd = Bs + st * BN * AKP;
        #pragma unroll
        for (int u = 0; u < 2; u++) {
            int c = tid + (u << 8);
            int m = c >> 2, k4 = c & 3;
            cp16(Ad + m * AKP + k4 * 4, Aq + (size_t)(m0 + m) * Hh + kt * BK + k4 * 4);
        }
        #pragma unroll
        for (int u = 0; u < 2; u++) {
            int c = tid + (u << 8);
            int n = c >> 2, k4 = c & 3;
            cp16(Bd + n * AKP + k4 * 4, keyrow(n0 + n) + kt * BK + k4 * 4);
        }
        cp_commit();
    };

    float acc[2][8][4];
    #pragma unroll
    for (int i = 0; i < 2; i++)
        #pragma unroll
        for (int j = 0; j < 8; j++)
            #pragma unroll
            for (int t = 0; t < 4; t++) acc[i][j][t] = 0.f;

    #pragma unroll
    for (int p = 0; p < ST - 1; p++) issue(p);

    for (int kt = 0; kt < KT; ++kt) {
        cp_wait<ST - 2>();
        __syncthreads();
        const float* Ab = As + (kt % ST) * BM * AKP;
        const float* Bbuf = Bs + (kt % ST) * BN * AKP;

        #pragma unroll
        for (int ks = 0; ks < 2; ks++) {
            const int kk = ks * 8 + lc;
            uint32_t af[2][4];
            #pragma unroll
            for (int mt = 0; mt < 2; mt++) {
                int r = wm * 32 + mt * 16 + lr;
                af[mt][0] = u32of(Ab[r * AKP + kk]);
                af[mt][1] = u32of(Ab[(r + 8) * AKP + kk]);
                af[mt][2] = u32of(Ab[r * AKP + kk + 4]);
                af[mt][3] = u32of(Ab[(r + 8) * AKP + kk + 4]);
            }
            uint32_t bf[8][2];
            #pragma unroll
            for (int nt = 0; nt < 8; nt++) {
                int cc = wn * 64 + nt * 8 + lr;
                bf[nt][0] = u32of(Bbuf[cc * AKP + kk]);
                bf[nt][1] = u32of(Bbuf[cc * AKP + kk + 4]);
            }
            #pragma unroll
            for (int mt = 0; mt < 2; mt++)
                #pragma unroll
                for (int nt = 0; nt < 8; nt++)
                    mma8(acc[mt][nt], af[mt], bf[nt]);
        }
        if (kt + ST - 1 < KT) issue(kt + ST - 1); else cp_commit();
    }

    const int L = past_lens[b];
    #pragma unroll
    for (int mt = 0; mt < 2; mt++) {
        #pragma unroll
        for (int nt = 0; nt < 8; nt++) {
            int c = n0 + wn * 64 + nt * 8 + lc * 2;
            #pragma unroll
            for (int half = 0; half < 2; half++) {
                int s = m0 + wm * 32 + mt * 16 + lr + half * 8;
                float v0 = acc[mt][nt][half * 2 + 0];
                float v1 = acc[mt][nt][half * 2 + 1];
                bool ok0 = (c < Pp) ? (c < L) : ((c - Pp) <= s);
                int c1 = c + 1;
                bool ok1 = (c1 < Pp) ? (c1 < L) : ((c1 - Pp) <= s);
                float o0 = ok0 ? v0 * SCALE : NEG_BIG;
                float o1 = ok1 ? v1 * SCALE : NEG_BIG;
                *reinterpret_cast<float2*>(scores + ((size_t)b * S_ + s) * Tt + c) =
                    make_float2(o0, o1);
            }
        }
    }
}

// ---------------------------------------------------------------------------
// PV: attn[b,s,:] = probs[b,s,:] @ V_all[b,:,:]   (K = T = 2304)
// ---------------------------------------------------------------------------
__global__ __launch_bounds__(256, 2)
void pv_tc(const float* __restrict__ probs, const float* __restrict__ past_v,
           const float* __restrict__ v_new, float* __restrict__ attn)
{
    extern __shared__ float sm[];
    float* As = sm;                       // [ST][BM][AKP]
    float* Bs = sm + ST * BM * AKP;       // [ST][BK][BNP]

    const int tid  = threadIdx.x;
    const int lane = tid & 31;
    const int warp = tid >> 5;
    const int wm   = warp & 3;
    const int wn   = warp >> 2;
    const int lr   = lane >> 2;
    const int lc   = lane & 3;
    const int b    = blockIdx.z;
    const int m0   = blockIdx.y * BM;
    const int n0   = blockIdx.x * BN;
    const int KT   = Tt / BK;   // 144

    const float* Ap = probs + (size_t)b * S_ * Tt;

    auto vrow = [&](int kidx) -> const float* {
        return (kidx < Pp) ? (past_v + ((size_t)b * Pp + kidx) * Hh)
                           : (v_new + ((size_t)b * S_ + (kidx - Pp)) * Hh);
    };
    auto issue = [&](int kt) {
        int st = kt % ST;
        float* Ad = As + st * BM * AKP;
        float* Bd = Bs + st * BK * BNP;
        #pragma unroll
        for (int u = 0; u < 2; u++) {
            int c = tid + (u << 8);
            int m = c >> 2, k4 = c & 3;
            cp16(Ad + m * AKP + k4 * 4, Ap + (size_t)(m0 + m) * Tt + kt * BK + k4 * 4);
        }
        #pragma unroll
        for (int u = 0; u < 2; u++) {
            int c = tid + (u << 8);
            int k = c >> 5, n4 = c & 31;
            cp16(Bd + k * BNP + n4 * 4, vrow(kt * BK + k) + n0 + n4 * 4);
        }
        cp_commit();
    };

    float acc[2][8][4];
    #pragma unroll
    for (int i = 0; i < 2; i++)
        #pragma unroll
        for (int j = 0; j < 8; j++)
            #pragma unroll
            for (int t = 0; t < 4; t++) acc[i][j][t] = 0.f;

    #pragma unroll
    for (int p = 0; p < ST - 1; p++) issue(p);

    for (int kt = 0; kt < KT; ++kt) {
        cp_wait<ST - 2>();
        __syncthreads();
        const float* Ab = As + (kt % ST) * BM * AKP;
        const float* Bbuf = Bs + (kt % ST) * BK * BNP;

        #pragma unroll
        for (int ks = 0; ks < 2; ks++) {
            const int kk = ks * 8 + lc;
            uint32_t af[2][4];
            #pragma unroll
            for (int mt = 0; mt < 2; mt++) {
                int r = wm * 32 + mt * 16 + lr;
                af[mt][0] = u32of(Ab[r * AKP + kk]);
                af[mt][1] = u32of(Ab[(r + 8) * AKP + kk]);
                af[mt][2] = u32of(Ab[r * AKP + kk + 4]);
                af[mt][3] = u32of(Ab[(r + 8) * AKP + kk + 4]);
            }
            uint32_t bf[8][2];
            #pragma unroll
            for (int nt = 0; nt < 8; nt++) {
                int cc = wn * 64 + nt * 8 + lr;
                bf[nt][0] = u32of(Bbuf[kk * BNP + cc]);
                bf[nt][1] = u32of(Bbuf[(kk + 4) * BNP + cc]);
            }
            #pragma unroll
            for (int mt = 0; mt < 2; mt++)
                #pragma unroll
                for (int nt = 0; nt < 8; nt++)
                    mma8(acc[mt][nt], af[mt], bf[nt]);
        }
        if (kt + ST - 1 < KT) issue(kt + ST - 1); else cp_commit();
    }

    #pragma unroll
    for (int mt = 0; mt < 2; mt++) {
        #pragma unroll
        for (int nt = 0; nt < 8; nt++) {
            int c = n0 + wn * 64 + nt * 8 + lc * 2;
            int r0 = m0 + wm * 32 + mt * 16 + lr;
            int r1 = r0 + 8;
            // rounded: g_at is only ever a GEMM A-operand
            *reinterpret_cast<float2*>(attn + ((size_t)b * S_ + r0) * Hh + c) =
                make_float2(rnd_tf32(acc[mt][nt][0]), rnd_tf32(acc[mt][nt][1]));
            *reinterpret_cast<float2*>(attn + ((size_t)b * S_ + r1) * Hh + c) =
                make_float2(rnd_tf32(acc[mt][nt][2]), rnd_tf32(acc[mt][nt][3]));
        }
    }
}

// ---------------------------------------------------------------------------
// Row softmax over T=2304; probs stored pre-rounded to tf32.
// ---------------------------------------------------------------------------
__global__ __launch_bounds__(256)
void softmax_kernel(float* __restrict__ scores)
{
    __shared__ float red[8];
    const int tid = threadIdx.x;
    float* p = scores + (size_t)blockIdx.x * Tt;

    float v[9];
    float mx = NEG_BIG;
    #pragma unroll
    for (int i = 0; i < 9; i++) { v[i] = p[tid + (i << 8)]; mx = fmaxf(mx, v[i]); }
    #pragma unroll
    for (int o = 16; o > 0; o >>= 1) mx = fmaxf(mx, __shfl_xor_sync(0xffffffffu, mx, o));
    if ((tid & 31) == 0) red[tid >> 5] = mx;
    __syncthreads();
    float m2 = red[0];
    #pragma unroll
    for (int i = 1; i < 8; i++) m2 = fmaxf(m2, red[i]);

    float sum = 0.f;
    #pragma unroll
    for (int i = 0; i < 9; i++) { v[i] = __expf(v[i] - m2); sum += v[i]; }
    #pragma unroll
    for (int o = 16; o > 0; o >>= 1) sum += __shfl_xor_sync(0xffffffffu, sum, o);
    __syncthreads();
    if ((tid & 31) == 0) red[tid >> 5] = sum;
    __syncthreads();
    float s2 = 0.f;
    #pragma unroll
    for (int i = 0; i < 8; i++) s2 += red[i];

    float inv = 1.f / s2;
    #pragma unroll
    for (int i = 0; i < 9; i++) p[tid + (i << 8)] = rnd_tf32(v[i] * inv);
}

// ---------------------------------------------------------------------------
// Launch
// ---------------------------------------------------------------------------
extern "C" void kernel_launch(void* const* d_in, const int* in_sizes, int n_in,
                              void* d_out, int out_size)
{
    const float* hidden    = (const float*)d_in[0];
    const float* past_k    = (const float*)d_in[1];
    const float* past_v    = (const float*)d_in[2];
    const int*   past_lens = (const int*)  d_in[3];
    const float* Wq = (const float*)d_in[4];
    const float* Wk = (const float*)d_in[6];
    const float* Wv = (const float*)d_in[8];
    const float* Wo = (const float*)d_in[10];
    const float* W1 = (const float*)d_in[12];
    const float* W2 = (const float*)d_in[14];
    const float* bq = (const float*)d_in[5];
    const float* bk = (const float*)d_in[7];
    const float* bv = (const float*)d_in[9];
    const float* bo = (const float*)d_in[11];
    const float* b1 = (const float*)d_in[13];
    const float* b2 = (const float*)d_in[15];
    float* out = (float*)d_out;

    float *q, *k, *v, *sc, *at, *h1, *h1r, *act, *hr, *wq, *wk, *wv, *wo, *w1, *w2;
    cudaGetSymbolAddress((void**)&q,   g_q);
    cudaGetSymbolAddress((void**)&k,   g_k);
    cudaGetSymbolAddress((void**)&v,   g_v);
    cudaGetSymbolAddress((void**)&sc,  g_sc);
    cudaGetSymbolAddress((void**)&at,  g_at);
    cudaGetSymbolAddress((void**)&h1,  g_h1);
    cudaGetSymbolAddress((void**)&h1r, g_h1r);
    cudaGetSymbolAddress((void**)&act, g_act);
    cudaGetSymbolAddress((void**)&hr,  g_hr);
    cudaGetSymbolAddress((void**)&wq,  g_wq);
    cudaGetSymbolAddress((void**)&wk,  g_wk);
    cudaGetSymbolAddress((void**)&wv,  g_wv);
    cudaGetSymbolAddress((void**)&wo,  g_wo);
    cudaGetSymbolAddress((void**)&w1,  g_w1);
    cudaGetSymbolAddress((void**)&w2,  g_w2);

    // Raise dynamic smem limits (idempotent)
    cudaFuncSetAttribute(gemm_tc<true,  E_BIAS,      true >, cudaFuncAttributeMaxDynamicSharedMemorySize, SMEM_GEMM);
    cudaFuncSetAttribute(gemm_tc<false, E_RES_HID,   false>, cudaFuncAttributeMaxDynamicSharedMemorySize, SMEM_GEMM);
    cudaFuncSetAttribute(gemm_tc<false, E_GELU,      true >, cudaFuncAttributeMaxDynamicSharedMemorySize, SMEM_GEMM);
    cudaFuncSetAttribute(gemm_tc<false, E_RES_TRANS, false>, cudaFuncAttributeMaxDynamicSharedMemorySize, SMEM_GEMM);
    cudaFuncSetAttribute(scores_tc, cudaFuncAttributeMaxDynamicSharedMemorySize, SMEM_SCORES);
    cudaFuncSetAttribute(pv_tc,     cudaFuncAttributeMaxDynamicSharedMemorySize, SMEM_GEMM);

    dim3 blk(256);

    // Pre-round inputs to tf32 (RNA): hidden + all weights
    round_copy<<<(Mm * Hh / 4 + 255) / 256, blk>>>(hidden, hr, Mm * Hh / 4);
    round_copy<<<(Hh * Hh / 4 + 255) / 256, blk>>>(Wq, wq, Hh * Hh / 4);
    round_copy<<<(Hh * Hh / 4 + 255) / 256, blk>>>(Wk, wk, Hh * Hh / 4);
    round_copy<<<(Hh * Hh / 4 + 255) / 256, blk>>>(Wv, wv, Hh * Hh / 4);
    round_copy<<<(Hh * Hh / 4 + 255) / 256, blk>>>(Wo, wo, Hh * Hh / 4);
    round_copy<<<(Hh * Ff / 4 + 255) / 256, blk>>>(W1, w1, Hh * Ff / 4);
    round_copy<<<(Ff * Hh / 4 + 255) / 256, blk>>>(W2, w2, Ff * Hh / 4);

    dim3 gProj(Hh / BN, Mm / BM);   // (4, 64)

    // QKV projections (outputs rounded)
    gemm_tc<true, E_BIAS, true><<<gProj, blk, SMEM_GEMM>>>(hr, wq, bq, nullptr, q, nullptr, Hh, Hh);
    gemm_tc<true, E_BIAS, true><<<gProj, blk, SMEM_GEMM>>>(hr, wk, bk, nullptr, k, nullptr, Hh, Hh);
    gemm_tc<true, E_BIAS, true><<<gProj, blk, SMEM_GEMM>>>(hr, wv, bv, nullptr, v, nullptr, Hh, Hh);

    // Attention
    scores_tc<<<dim3(Tt / BN, S_ / BM, Bb), blk, SMEM_SCORES>>>(q, past_k, k, past_lens, sc);
    softmax_kernel<<<Mm, blk>>>(sc);
    pv_tc<<<dim3(Hh / BN, S_ / BM, Bb), blk, SMEM_GEMM>>>(sc, past_v, v, at);

    // Output projection + residual (residual from ORIGINAL hidden, exact)
    gemm_tc<false, E_RES_HID, false><<<gProj, blk, SMEM_GEMM>>>(at, wo, bo, hidden, h1, h1r, Hh, Hh);

    // FFN
    gemm_tc<false, E_GELU, true><<<dim3(Ff / BN, Mm / BM), blk, SMEM_GEMM>>>(h1r, w1, b1, nullptr, act, nullptr, Hh, Ff);
    gemm_tc<false, E_RES_TRANS, false><<<gProj, blk, SMEM_GEMM>>>(act, w2, b2, h1, out, nullptr, Ff, Hh);
}

// round 4
// speedup vs baseline: 3.9374x; 1.0643x over previous
#include <cuda_runtime.h>
#include <cuda_bf16.h>
#include <math.h>
#include <stdint.h>

// Problem constants
constexpr int S_ = 256;
constexpr int Bb = 32;
constexpr int Hh = 512;
constexpr int Pp = 2048;
constexpr int Tt = Pp + S_;     // 2304
constexpr int Mm = Bb * S_;     // 8192
constexpr int Ff = 4 * Hh;      // 2048
constexpr int QKVN = 3 * Hh;    // 1536

constexpr float SCALE = 0.044194173824159223f;  // 1/sqrt(512)
constexpr float NEG_BIG = -1.0e30f;

// Scratch
__device__ float g_qkv[(size_t)Mm * QKVN];   // packed q|k|v per row
__device__ float g_sc[(size_t)Mm * Tt];
__device__ float g_at[(size_t)Mm * Hh];
__device__ float g_h1[(size_t)Mm * Hh];      // exact (residual)
__device__ float g_h1r[(size_t)Mm * Hh];     // rounded (FFN-A)
__device__ float g_act[(size_t)Mm * Ff];
// Pre-rounded inputs
__device__ float g_hr[(size_t)Mm * Hh];
__device__ float g_wqkv[Hh * QKVN];          // [k][1536] packed
__device__ float g_bqkv[QKVN];
__device__ float g_wo[Hh * Hh];
__device__ float g_w1[Hh * Ff];
__device__ float g_w2[Ff * Hh];

// hidden is [S, B, H]; logical row m = b*S + s maps to hidden[(s*B + b)*H]
__device__ __forceinline__ size_t hid_off(int m) {
    int b = m >> 8;
    int s = m & (S_ - 1);
    return ((size_t)s * Bb + b) * Hh;
}

__device__ __forceinline__ float rnd_tf32(float x) {
    uint32_t u;
    asm("cvt.rna.tf32.f32 %0, %1;" : "=r"(u) : "f"(x));
    return __uint_as_float(u);
}

__device__ __forceinline__ void mma8(float* d, const uint32_t* a, const uint32_t* b) {
    asm volatile(
        "mma.sync.aligned.m16n8k8.row.col.f32.tf32.tf32.f32 "
        "{%0,%1,%2,%3},{%4,%5,%6,%7},{%8,%9},{%0,%1,%2,%3};"
        : "+f"(d[0]), "+f"(d[1]), "+f"(d[2]), "+f"(d[3])
        : "r"(a[0]), "r"(a[1]), "r"(a[2]), "r"(a[3]), "r"(b[0]), "r"(b[1]));
}

__device__ __forceinline__ void cp16(void* smem, const void* g) {
    uint32_t s = (uint32_t)__cvta_generic_to_shared(smem);
    asm volatile("cp.async.cg.shared.global [%0], [%1], 16;" :: "r"(s), "l"(g));
}
__device__ __forceinline__ void cp_commit() { asm volatile("cp.async.commit_group;"); }
template<int N>
__device__ __forceinline__ void cp_wait() { asm volatile("cp.async.wait_group %0;" :: "n"(N)); }

__device__ __forceinline__ uint32_t u32of(float f) { return __float_as_uint(f); }

#define BM 128
#define BN 128
#define BK 16
#define AKP 20     // [row][k] stride (k padded)
#define BNP 136    // [k][n] stride (n padded)
#define ST 4       // pipeline stages
#define NT 128     // threads per CTA (4 warps, 64x64 warp tiles)

enum { E_BIAS = 0, E_GELU = 1, E_RES_HID = 2, E_RES_TRANS = 3 };

constexpr int SMEM_GEMM   = ST * (BM * AKP + BK * BNP) * 4;   // 75776 B
constexpr int SMEM_SCORES = ST * (BM * AKP + BN * AKP) * 4;   // 81920 B

// ---------------------------------------------------------------------------
// Unified prep: round hidden/weights to tf32 (RNA) and pack QKV weights+bias.
// Region table in float4 units.
// ---------------------------------------------------------------------------
constexpr int F4_HR   = Mm * Hh / 4;        // 1048576
constexpr int F4_WO   = Hh * Hh / 4;        // 65536
constexpr int F4_W1   = Hh * Ff / 4;        // 262144
constexpr int F4_W2   = Ff * Hh / 4;        // 262144
constexpr int F4_WQKV = Hh * QKVN / 4;      // 196608
constexpr int F4_BQKV = QKVN / 4;           // 384
constexpr int F4_TOTAL = F4_HR + F4_WO + F4_W1 + F4_W2 + F4_WQKV + F4_BQKV;

__global__ __launch_bounds__(256)
void prep_kernel(const float* __restrict__ hidden,
                 const float* __restrict__ Wq, const float* __restrict__ Wk,
                 const float* __restrict__ Wv, const float* __restrict__ Wo,
                 const float* __restrict__ W1, const float* __restrict__ W2,
                 const float* __restrict__ bq, const float* __restrict__ bk,
                 const float* __restrict__ bv)
{
    int i = blockIdx.x * blockDim.x + threadIdx.x;
    if (i >= F4_TOTAL) return;

    auto rc = [](const float* s, float* d, int idx) {
        float4 v = reinterpret_cast<const float4*>(s)[idx];
        v.x = rnd_tf32(v.x); v.y = rnd_tf32(v.y);
        v.z = rnd_tf32(v.z); v.w = rnd_tf32(v.w);
        reinterpret_cast<float4*>(d)[idx] = v;
    };

    if (i < F4_HR) { rc(hidden, g_hr, i); return; }
    i -= F4_HR;
    if (i < F4_WO) { rc(Wo, g_wo, i); return; }
    i -= F4_WO;
    if (i < F4_W1) { rc(W1, g_w1, i); return; }
    i -= F4_W1;
    if (i < F4_W2) { rc(W2, g_w2, i); return; }
    i -= F4_W2;
    if (i < F4_WQKV) {
        int row = i / (QKVN / 4);        // k index 0..511
        int j4  = i % (QKVN / 4);        // 0..383
        int sel = j4 >> 7;               // 0..2
        int col4 = j4 & 127;             // within source matrix
        const float* src = (sel == 0) ? Wq : (sel == 1) ? Wk : Wv;
        float4 v = reinterpret_cast<const float4*>(src + (size_t)row * Hh)[col4];
        v.x = rnd_tf32(v.x); v.y = rnd_tf32(v.y);
        v.z = rnd_tf32(v.z); v.w = rnd_tf32(v.w);
        reinterpret_cast<float4*>(g_wqkv + (size_t)row * QKVN)[j4] = v;
        return;
    }
    i -= F4_WQKV;
    {
        int sel = i >> 7;
        int col4 = i & 127;
        const float* src = (sel == 0) ? bq : (sel == 1) ? bk : bv;
        reinterpret_cast<float4*>(g_bqkv)[i] = reinterpret_cast<const float4*>(src)[col4];
    }
}

// ---------------------------------------------------------------------------
// GEMM core mainloop (64x64 warp tiles, 4 warps): shared by all kernels.
// ---------------------------------------------------------------------------
struct Frag {
    float acc[4][8][4];
    __device__ __forceinline__ void zero() {
        #pragma unroll
        for (int i = 0; i < 4; i++)
            #pragma unroll
            for (int j = 0; j < 8; j++)
                #pragma unroll
                for (int t = 0; t < 4; t++) acc[i][j][t] = 0.f;
    }
};

// Compute one BK=16 tile given smem bases. BMAJOR_N: B stored [k][n] (stride BNP)
// else [n][k] (stride AKP).
template<bool BKN>
__device__ __forceinline__ void tile_mma(Frag& F, const float* Ab, const float* Bbuf,
                                         int wm, int wn, int lr, int lc)
{
    #pragma unroll
    for (int ks = 0; ks < 2; ks++) {
        const int kk = ks * 8 + lc;
        uint32_t af[4][4];
        #pragma unroll
        for (int mt = 0; mt < 4; mt++) {
            int r = wm * 64 + mt * 16 + lr;
            af[mt][0] = u32of(Ab[r * AKP + kk]);
            af[mt][1] = u32of(Ab[(r + 8) * AKP + kk]);
            af[mt][2] = u32of(Ab[r * AKP + kk + 4]);
            af[mt][3] = u32of(Ab[(r + 8) * AKP + kk + 4]);
        }
        uint32_t bf[8][2];
        #pragma unroll
        for (int nt = 0; nt < 8; nt++) {
            int cc = wn * 64 + nt * 8 + lr;
            if (BKN) {
                bf[nt][0] = u32of(Bbuf[kk * BNP + cc]);
                bf[nt][1] = u32of(Bbuf[(kk + 4) * BNP + cc]);
            } else {
                bf[nt][0] = u32of(Bbuf[cc * AKP + kk]);
                bf[nt][1] = u32of(Bbuf[cc * AKP + kk + 4]);
            }
        }
        #pragma unroll
        for (int mt = 0; mt < 4; mt++)
            #pragma unroll
            for (int nt = 0; nt < 8; nt++)
                mma8(F.acc[mt][nt], af[mt], bf[nt]);
    }
}

// ---------------------------------------------------------------------------
// Standard GEMM: C[M,N] = A[M,K] @ W[K,N] + bias (+ epilogue)
// ---------------------------------------------------------------------------
template<bool AHID, int EPI, bool ROUND>
__global__ __launch_bounds__(NT, 2)
void gemm_tc(const float* __restrict__ A, const float* __restrict__ W,
             const float* __restrict__ bias, const float* __restrict__ R,
             float* __restrict__ C, float* __restrict__ C2, int K, int N, int CN)
{
    extern __shared__ float sm[];
    float* As = sm;                       // [ST][BM][AKP]
    float* Bs = sm + ST * BM * AKP;       // [ST][BK][BNP]

    const int tid  = threadIdx.x;
    const int lane = tid & 31;
    const int warp = tid >> 5;
    const int wm   = warp & 1;
    const int wn   = warp >> 1;
    const int lr   = lane >> 2;
    const int lc   = lane & 3;
    const int m0   = blockIdx.y * BM;
    const int n0   = blockIdx.x * BN;
    const int KT   = K / BK;

    auto issue = [&](int kt) {
        int st = kt % ST;
        float* Ad = As + st * BM * AKP;
        float* Bd = Bs + st * BK * BNP;
        #pragma unroll
        for (int u = 0; u < 4; u++) {
            int c = tid + u * NT;
            int m = c >> 2, k4 = c & 3;
            const float* g = (AHID ? (A + hid_off(m0 + m)) : (A + (size_t)(m0 + m) * K))
                             + kt * BK + k4 * 4;
            cp16(Ad + m * AKP + k4 * 4, g);
        }
        #pragma unroll
        for (int u = 0; u < 4; u++) {
            int c = tid + u * NT;
            int k = c >> 5, n4 = c & 31;
            cp16(Bd + k * BNP + n4 * 4, W + (size_t)(kt * BK + k) * N + n0 + n4 * 4);
        }
        cp_commit();
    };

    Frag F; F.zero();

    #pragma unroll
    for (int p = 0; p < ST - 1; p++) issue(p);

    for (int kt = 0; kt < KT; ++kt) {
        cp_wait<ST - 2>();
        __syncthreads();
        tile_mma<true>(F, As + (kt % ST) * BM * AKP, Bs + (kt % ST) * BK * BNP,
                       wm, wn, lr, lc);
        if (kt + ST - 1 < KT) issue(kt + ST - 1); else cp_commit();
        __syncthreads();
    }

    // Epilogue
    #pragma unroll
    for (int nt = 0; nt < 8; nt++) {
        int c = n0 + wn * 64 + nt * 8 + lc * 2;
        float bv0 = bias[c], bv1 = bias[c + 1];
        #pragma unroll
        for (int mt = 0; mt < 4; mt++) {
            int r0 = m0 + wm * 64 + mt * 16 + lr;
            int r1 = r0 + 8;
            float v00 = F.acc[mt][nt][0] + bv0;
            float v01 = F.acc[mt][nt][1] + bv1;
            float v10 = F.acc[mt][nt][2] + bv0;
            float v11 = F.acc[mt][nt][3] + bv1;
            if (EPI == E_GELU) {
                v00 = 0.5f * v00 * (1.f + erff(v00 * 0.70710678118654752f));
                v01 = 0.5f * v01 * (1.f + erff(v01 * 0.70710678118654752f));
                v10 = 0.5f * v10 * (1.f + erff(v10 * 0.70710678118654752f));
                v11 = 0.5f * v11 * (1.f + erff(v11 * 0.70710678118654752f));
            } else if (EPI == E_RES_HID) {
                const float* rp0 = R + hid_off(r0) + c;
                const float* rp1 = R + hid_off(r1) + c;
                v00 += rp0[0]; v01 += rp0[1];
                v10 += rp1[0]; v11 += rp1[1];
            } else if (EPI == E_RES_TRANS) {
                const float* rp0 = R + (size_t)r0 * CN + c;
                const float* rp1 = R + (size_t)r1 * CN + c;
                v00 += rp0[0]; v01 += rp0[1];
                v10 += rp1[0]; v11 += rp1[1];
            }
            if (EPI == E_RES_HID) {
                *reinterpret_cast<float2*>(C  + (size_t)r0 * CN + c) = make_float2(v00, v01);
                *reinterpret_cast<float2*>(C  + (size_t)r1 * CN + c) = make_float2(v10, v11);
                *reinterpret_cast<float2*>(C2 + (size_t)r0 * CN + c) =
                    make_float2(rnd_tf32(v00), rnd_tf32(v01));
                *reinterpret_cast<float2*>(C2 + (size_t)r1 * CN + c) =
                    make_float2(rnd_tf32(v10), rnd_tf32(v11));
            } else {
                if (ROUND) {
                    v00 = rnd_tf32(v00); v01 = rnd_tf32(v01);
                    v10 = rnd_tf32(v10); v11 = rnd_tf32(v11);
                }
                if (EPI == E_RES_TRANS) {
                    *reinterpret_cast<float2*>(C + hid_off(r0) + c) = make_float2(v00, v01);
                    *reinterpret_cast<float2*>(C + hid_off(r1) + c) = make_float2(v10, v11);
                } else {
                    *reinterpret_cast<float2*>(C + (size_t)r0 * CN + c) = make_float2(v00, v01);
                    *reinterpret_cast<float2*>(C + (size_t)r1 * CN + c) = make_float2(v10, v11);
                }
            }
        }
    }
}

// ---------------------------------------------------------------------------
// Scores: scores[b,s,j] = q[b,s,:] . K_all[b,j,:] * SCALE, masked.
// q rows / k_new rows live in packed qkv buffer (stride QKVN).
// ---------------------------------------------------------------------------
__global__ __launch_bounds__(NT, 2)
void scores_tc(const float* __restrict__ qkv, const float* __restrict__ past_k,
               const int* __restrict__ past_lens, float* __restrict__ scores)
{
    extern __shared__ float sm[];
    float* As = sm;                       // [ST][BM][AKP]
    float* Bs = sm + ST * BM * AKP;       // [ST][BN][AKP]

    const int tid  = threadIdx.x;
    const int lane = tid & 31;
    const int warp = tid >> 5;
    const int wm   = warp & 1;
    const int wn   = warp >> 1;
    const int lr   = lane >> 2;
    const int lc   = lane & 3;
    const int b    = blockIdx.z;
    const int m0   = blockIdx.y * BM;
    const int n0   = blockIdx.x * BN;
    const int KT   = Hh / BK;   // 32

    const float* Aq = qkv + (size_t)b * S_ * QKVN;   // q at col offset 0

    auto keyrow = [&](int j) -> const float* {
        return (j < Pp) ? (past_k + ((size_t)b * Pp + j) * Hh)
                        : (qkv + ((size_t)b * S_ + (j - Pp)) * QKVN + Hh);
    };
    auto issue = [&](int kt) {
        int st = kt % ST;
        float* Ad = As + st * BM * AKP;
        float* Bd = Bs + st * BN * AKP;
        #pragma unroll
        for (int u = 0; u < 4; u++) {
            int c = tid + u * NT;
            int m = c >> 2, k4 = c & 3;
            cp16(Ad + m * AKP + k4 * 4, Aq + (size_t)(m0 + m) * QKVN + kt * BK + k4 * 4);
        }
        #pragma unroll
        for (int u = 0; u < 4; u++) {
            int c = tid + u * NT;
            int n = c >> 2, k4 = c & 3;
            cp16(Bd + n * AKP + k4 * 4, keyrow(n0 + n) + kt * BK + k4 * 4);
        }
        cp_commit();
    };

    Frag F; F.zero();

    #pragma unroll
    for (int p = 0; p < ST - 1; p++) issue(p);

    for (int kt = 0; kt < KT; ++kt) {
        cp_wait<ST - 2>();
        __syncthreads();
        tile_mma<false>(F, As + (kt % ST) * BM * AKP, Bs + (kt % ST) * BN * AKP,
                        wm, wn, lr, lc);
        if (kt + ST - 1 < KT) issue(kt + ST - 1); else cp_commit();
        __syncthreads();
    }

    const int L = past_lens[b];
    #pragma unroll
    for (int mt = 0; mt < 4; mt++) {
        #pragma unroll
        for (int nt = 0; nt < 8; nt++) {
            int c = n0 + wn * 64 + nt * 8 + lc * 2;
            #pragma unroll
            for (int half = 0; half < 2; half++) {
                int s = m0 + wm * 64 + mt * 16 + lr + half * 8;
                float v0 = F.acc[mt][nt][half * 2 + 0];
                float v1 = F.acc[mt][nt][half * 2 + 1];
                bool ok0 = (c < Pp) ? (c < L) : ((c - Pp) <= s);
                int c1 = c + 1;
                bool ok1 = (c1 < Pp) ? (c1 < L) : ((c1 - Pp) <= s);
                float o0 = ok0 ? v0 * SCALE : NEG_BIG;
                float o1 = ok1 ? v1 * SCALE : NEG_BIG;
                *reinterpret_cast<float2*>(scores + ((size_t)b * S_ + s) * Tt + c) =
                    make_float2(o0, o1);
            }
        }
    }
}

// ---------------------------------------------------------------------------
// PV: attn[b,s,:] = probs[b,s,:] @ V_all[b,:,:]   (K = T = 2304)
// v_new rows live in packed qkv buffer at col offset 1024.
// ---------------------------------------------------------------------------
__global__ __launch_bounds__(NT, 2)
void pv_tc(const float* __restrict__ probs, const float* __restrict__ past_v,
           const float* __restrict__ qkv, float* __restrict__ attn)
{
    extern __shared__ float sm[];
    float* As = sm;                       // [ST][BM][AKP]
    float* Bs = sm + ST * BM * AKP;       // [ST][BK][BNP]

    const int tid  = threadIdx.x;
    const int lane = tid & 31;
    const int warp = tid >> 5;
    const int wm   = warp & 1;
    const int wn   = warp >> 1;
    const int lr   = lane >> 2;
    const int lc   = lane & 3;
    const int b    = blockIdx.z;
    const int m0   = blockIdx.y * BM;
    const int n0   = blockIdx.x * BN;
    const int KT   = Tt / BK;   // 144

    const float* Ap = probs + (size_t)b * S_ * Tt;

    auto vrow = [&](int kidx) -> const float* {
        return (kidx < Pp) ? (past_v + ((size_t)b * Pp + kidx) * Hh)
                           : (qkv + ((size_t)b * S_ + (kidx - Pp)) * QKVN + 2 * Hh);
    };
    auto issue = [&](int kt) {
        int st = kt % ST;
        float* Ad = As + st * BM * AKP;
        float* Bd = Bs + st * BK * BNP;
        #pragma unroll
        for (int u = 0; u < 4; u++) {
            int c = tid + u * NT;
            int m = c >> 2, k4 = c & 3;
            cp16(Ad + m * AKP + k4 * 4, Ap + (size_t)(m0 + m) * Tt + kt * BK + k4 * 4);
        }
        #pragma unroll
        for (int u = 0; u < 4; u++) {
            int c = tid + u * NT;
            int k = c >> 5, n4 = c & 31;
            cp16(Bd + k * BNP + n4 * 4, vrow(kt * BK + k) + n0 + n4 * 4);
        }
        cp_commit();
    };

    Frag F; F.zero();

    #pragma unroll
    for (int p = 0; p < ST - 1; p++) issue(p);

    for (int kt = 0; kt < KT; ++kt) {
        cp_wait<ST - 2>();
        __syncthreads();
        tile_mma<true>(F, As + (kt % ST) * BM * AKP, Bs + (kt % ST) * BK * BNP,
                       wm, wn, lr, lc);
        if (kt + ST - 1 < KT) issue(kt + ST - 1); else cp_commit();
        __syncthreads();
    }

    #pragma unroll
    for (int mt = 0; mt < 4; mt++) {
        #pragma unroll
        for (int nt = 0; nt < 8; nt++) {
            int c = n0 + wn * 64 + nt * 8 + lc * 2;
            int r0 = m0 + wm * 64 + mt * 16 + lr;
            int r1 = r0 + 8;
            *reinterpret_cast<float2*>(attn + ((size_t)b * S_ + r0) * Hh + c) =
                make_float2(rnd_tf32(F.acc[mt][nt][0]), rnd_tf32(F.acc[mt][nt][1]));
            *reinterpret_cast<float2*>(attn + ((size_t)b * S_ + r1) * Hh + c) =
                make_float2(rnd_tf32(F.acc[mt][nt][2]), rnd_tf32(F.acc[mt][nt][3]));
        }
    }
}

// ---------------------------------------------------------------------------
// Row softmax over T=2304; probs stored pre-rounded to tf32.
// ---------------------------------------------------------------------------
__global__ __launch_bounds__(256)
void softmax_kernel(float* __restrict__ scores)
{
    __shared__ float red[8];
    const int tid = threadIdx.x;
    float* p = scores + (size_t)blockIdx.x * Tt;

    float v[9];
    float mx = NEG_BIG;
    #pragma unroll
    for (int i = 0; i < 9; i++) { v[i] = p[tid + (i << 8)]; mx = fmaxf(mx, v[i]); }
    #pragma unroll
    for (int o = 16; o > 0; o >>= 1) mx = fmaxf(mx, __shfl_xor_sync(0xffffffffu, mx, o));
    if ((tid & 31) == 0) red[tid >> 5] = mx;
    __syncthreads();
    float m2 = red[0];
    #pragma unroll
    for (int i = 1; i < 8; i++) m2 = fmaxf(m2, red[i]);

    float sum = 0.f;
    #pragma unroll
    for (int i = 0; i < 9; i++) { v[i] = __expf(v[i] - m2); sum += v[i]; }
    #pragma unroll
    for (int o = 16; o > 0; o >>= 1) sum += __shfl_xor_sync(0xffffffffu, sum, o);
    __syncthreads();
    if ((tid & 31) == 0) red[tid >> 5] = sum;
    __syncthreads();
    float s2 = 0.f;
    #pragma unroll
    for (int i = 0; i < 8; i++) s2 += red[i];

    float inv = 1.f / s2;
    #pragma unroll
    for (int i = 0; i < 9; i++) p[tid + (i << 8)] = rnd_tf32(v[i] * inv);
}

// ---------------------------------------------------------------------------
// Launch
// ---------------------------------------------------------------------------
extern "C" void kernel_launch(void* const* d_in, const int* in_sizes, int n_in,
                              void* d_out, int out_size)
{
    const float* hidden    = (const float*)d_in[0];
    const float* past_k    = (const float*)d_in[1];
    const float* past_v    = (const float*)d_in[2];
    const int*   past_lens = (const int*)  d_in[3];
    const float* Wq = (const float*)d_in[4];  const float* bq = (const float*)d_in[5];
    const float* Wk = (const float*)d_in[6];  const float* bk = (const float*)d_in[7];
    const float* Wv = (const float*)d_in[8];  const float* bv = (const float*)d_in[9];
    const float* Wo = (const float*)d_in[10]; const float* bo = (const float*)d_in[11];
    const float* W1 = (const float*)d_in[12]; const float* b1 = (const float*)d_in[13];
    const float* W2 = (const float*)d_in[14]; const float* b2 = (const float*)d_in[15];
    float* out = (float*)d_out;

    float *qkv, *sc, *at, *h1, *h1r, *act, *hr, *wqkv, *bqkv, *wo, *w1, *w2;
    cudaGetSymbolAddress((void**)&qkv,  g_qkv);
    cudaGetSymbolAddress((void**)&sc,   g_sc);
    cudaGetSymbolAddress((void**)&at,   g_at);
    cudaGetSymbolAddress((void**)&h1,   g_h1);
    cudaGetSymbolAddress((void**)&h1r,  g_h1r);
    cudaGetSymbolAddress((void**)&act,  g_act);
    cudaGetSymbolAddress((void**)&hr,   g_hr);
    cudaGetSymbolAddress((void**)&wqkv, g_wqkv);
    cudaGetSymbolAddress((void**)&bqkv, g_bqkv);
    cudaGetSymbolAddress((void**)&wo,   g_wo);
    cudaGetSymbolAddress((void**)&w1,   g_w1);
    cudaGetSymbolAddress((void**)&w2,   g_w2);

    cudaFuncSetAttribute(gemm_tc<true,  E_BIAS,      true >, cudaFuncAttributeMaxDynamicSharedMemorySize, SMEM_GEMM);
    cudaFuncSetAttribute(gemm_tc<false, E_RES_HID,   false>, cudaFuncAttributeMaxDynamicSharedMemorySize, SMEM_GEMM);
    cudaFuncSetAttribute(gemm_tc<false, E_GELU,      true >, cudaFuncAttributeMaxDynamicSharedMemorySize, SMEM_GEMM);
    cudaFuncSetAttribute(gemm_tc<false, E_RES_TRANS, false>, cudaFuncAttributeMaxDynamicSharedMemorySize, SMEM_GEMM);
    cudaFuncSetAttribute(scores_tc, cudaFuncAttributeMaxDynamicSharedMemorySize, SMEM_SCORES);
    cudaFuncSetAttribute(pv_tc,     cudaFuncAttributeMaxDynamicSharedMemorySize, SMEM_GEMM);

    // Prep: round + pack (single launch)
    prep_kernel<<<(F4_TOTAL + 255) / 256, 256>>>(hidden, Wq, Wk, Wv, Wo, W1, W2, bq, bk, bv);

    dim3 blk(NT);

    // Fused QKV projection: [8192, 1536]
    gemm_tc<true, E_BIAS, true><<<dim3(QKVN / BN, Mm / BM), blk, SMEM_GEMM>>>(
        hr, wqkv, bqkv, nullptr, qkv, nullptr, Hh, QKVN, QKVN);

    // Attention
    scores_tc<<<dim3(Tt / BN, S_ / BM, Bb), blk, SMEM_SCORES>>>(qkv, past_k, past_lens, sc);
    softmax_kernel<<<Mm, 256>>>(sc);
    pv_tc<<<dim3(Hh / BN, S_ / BM, Bb), blk, SMEM_GEMM>>>(sc, past_v, qkv, at);

    // Output projection + residual (residual from ORIGINAL hidden, exact)
    gemm_tc<false, E_RES_HID, false><<<dim3(Hh / BN, Mm / BM), blk, SMEM_GEMM>>>(
        at, wo, bo, hidden, h1, h1r, Hh, Hh, Hh);

    // FFN
    gemm_tc<false, E_GELU, true><<<dim3(Ff / BN, Mm / BM), blk, SMEM_GEMM>>>(
        h1r, w1, b1, nullptr, act, nullptr, Hh, Ff, Ff);
    gemm_tc<false, E_RES_TRANS, false><<<dim3(Hh / BN, Mm / BM), blk, SMEM_GEMM>>>(
        act, w2, b2, h1, out, nullptr, Ff, Hh, Hh);
}

// round 5
// speedup vs baseline: 4.3233x; 1.0980x over previous
#include <cuda_runtime.h>
#include <cuda_bf16.h>
#include <math.h>
#include <stdint.h>

// Problem constants
constexpr int S_ = 256;
constexpr int Bb = 32;
constexpr int Hh = 512;
constexpr int Pp = 2048;
constexpr int Tt = Pp + S_;     // 2304
constexpr int Mm = Bb * S_;     // 8192
constexpr int Ff = 4 * Hh;      // 2048
constexpr int QKVN = 3 * Hh;    // 1536

constexpr float SCALE = 0.044194173824159223f;  // 1/sqrt(512)
constexpr float NEG_BIG = -1.0e30f;

// Scratch
__device__ float g_qkv[(size_t)Mm * QKVN];
__device__ float g_sc[(size_t)Mm * Tt];
__device__ float g_at[(size_t)Mm * Hh];
__device__ float g_h1[(size_t)Mm * Hh];      // exact (residual)
__device__ float g_h1r[(size_t)Mm * Hh];     // rounded (FFN-A)
__device__ float g_act[(size_t)Mm * Ff];
// Pre-rounded inputs
__device__ float g_hr[(size_t)Mm * Hh];
__device__ float g_wqkv[Hh * QKVN];
__device__ float g_bqkv[QKVN];
__device__ float g_wo[Hh * Hh];
__device__ float g_w1[Hh * Ff];
__device__ float g_w2[Ff * Hh];

__device__ __forceinline__ size_t hid_off(int m) {
    int b = m >> 8;
    int s = m & (S_ - 1);
    return ((size_t)s * Bb + b) * Hh;
}

__device__ __forceinline__ float rnd_tf32(float x) {
    uint32_t u;
    asm("cvt.rna.tf32.f32 %0, %1;" : "=r"(u) : "f"(x));
    return __uint_as_float(u);
}

__device__ __forceinline__ void mma8(float* d, const uint32_t* a, const uint32_t* b) {
    asm volatile(
        "mma.sync.aligned.m16n8k8.row.col.f32.tf32.tf32.f32 "
        "{%0,%1,%2,%3},{%4,%5,%6,%7},{%8,%9},{%0,%1,%2,%3};"
        : "+f"(d[0]), "+f"(d[1]), "+f"(d[2]), "+f"(d[3])
        : "r"(a[0]), "r"(a[1]), "r"(a[2]), "r"(a[3]), "r"(b[0]), "r"(b[1]));
}

__device__ __forceinline__ void cp16(void* smem, const void* g) {
    uint32_t s = (uint32_t)__cvta_generic_to_shared(smem);
    asm volatile("cp.async.cg.shared.global [%0], [%1], 16;" :: "r"(s), "l"(g));
}
__device__ __forceinline__ void cp_commit() { asm volatile("cp.async.commit_group;"); }
template<int N>
__device__ __forceinline__ void cp_wait() { asm volatile("cp.async.wait_group %0;" :: "n"(N)); }

__device__ __forceinline__ uint32_t u32of(float f) { return __float_as_uint(f); }

#define BM 128
#define BN 128
#define BK 16
#define AKP 20
#define BNP 136
#define ST 4
#define NT 128

enum { E_BIAS = 0, E_GELU = 1, E_RES_HID = 2, E_RES_TRANS = 3 };

constexpr int SMEM_GEMM   = ST * (BM * AKP + BK * BNP) * 4;
constexpr int SMEM_SCORES = ST * (BM * AKP + BN * AKP) * 4;

// ---------------------------------------------------------------------------
// Prep: round to tf32 (RNA), pack QKV weights+bias.
// ---------------------------------------------------------------------------
constexpr int F4_HR   = Mm * Hh / 4;
constexpr int F4_WO   = Hh * Hh / 4;
constexpr int F4_W1   = Hh * Ff / 4;
constexpr int F4_W2   = Ff * Hh / 4;
constexpr int F4_WQKV = Hh * QKVN / 4;
constexpr int F4_BQKV = QKVN / 4;
constexpr int F4_TOTAL = F4_HR + F4_WO + F4_W1 + F4_W2 + F4_WQKV + F4_BQKV;

__global__ __launch_bounds__(256)
void prep_kernel(const float* __restrict__ hidden,
                 const float* __restrict__ Wq, const float* __restrict__ Wk,
                 const float* __restrict__ Wv, const float* __restrict__ Wo,
                 const float* __restrict__ W1, const float* __restrict__ W2,
                 const float* __restrict__ bq, const float* __restrict__ bk,
                 const float* __restrict__ bv)
{
    int i = blockIdx.x * blockDim.x + threadIdx.x;
    if (i >= F4_TOTAL) return;

    auto rc = [](const float* s, float* d, int idx) {
        float4 v = reinterpret_cast<const float4*>(s)[idx];
        v.x = rnd_tf32(v.x); v.y = rnd_tf32(v.y);
        v.z = rnd_tf32(v.z); v.w = rnd_tf32(v.w);
        reinterpret_cast<float4*>(d)[idx] = v;
    };

    if (i < F4_HR) { rc(hidden, g_hr, i); return; }
    i -= F4_HR;
    if (i < F4_WO) { rc(Wo, g_wo, i); return; }
    i -= F4_WO;
    if (i < F4_W1) { rc(W1, g_w1, i); return; }
    i -= F4_W1;
    if (i < F4_W2) { rc(W2, g_w2, i); return; }
    i -= F4_W2;
    if (i < F4_WQKV) {
        int row = i / (QKVN / 4);
        int j4  = i % (QKVN / 4);
        int sel = j4 >> 7;
        int col4 = j4 & 127;
        const float* src = (sel == 0) ? Wq : (sel == 1) ? Wk : Wv;
        float4 v = reinterpret_cast<const float4*>(src + (size_t)row * Hh)[col4];
        v.x = rnd_tf32(v.x); v.y = rnd_tf32(v.y);
        v.z = rnd_tf32(v.z); v.w = rnd_tf32(v.w);
        reinterpret_cast<float4*>(g_wqkv + (size_t)row * QKVN)[j4] = v;
        return;
    }
    i -= F4_WQKV;
    {
        int sel = i >> 7;
        int col4 = i & 127;
        const float* src = (sel == 0) ? bq : (sel == 1) ? bk : bv;
        reinterpret_cast<float4*>(g_bqkv)[i] = reinterpret_cast<const float4*>(src)[col4];
    }
}

// ---------------------------------------------------------------------------
// 64x64 warp-tile mainloop core. All fragments for both k-steps are loaded
// up front (64 regs) so the 64 MMAs stream without LDS dependency stalls.
// ---------------------------------------------------------------------------
struct Frag {
    float acc[4][8][4];
    __device__ __forceinline__ void zero() {
        #pragma unroll
        for (int i = 0; i < 4; i++)
            #pragma unroll
            for (int j = 0; j < 8; j++)
                #pragma unroll
                for (int t = 0; t < 4; t++) acc[i][j][t] = 0.f;
    }
};

template<bool BKN>
__device__ __forceinline__ void tile_mma(Frag& F, const float* Ab, const float* Bbuf,
                                         int wm, int wn, int lr, int lc)
{
    uint32_t af[2][4][4];
    uint32_t bf[2][8][2];
    #pragma unroll
    for (int ks = 0; ks < 2; ks++) {
        const int kk = ks * 8 + lc;
        #pragma unroll
        for (int mt = 0; mt < 4; mt++) {
            int r = wm * 64 + mt * 16 + lr;
            af[ks][mt][0] = u32of(Ab[r * AKP + kk]);
            af[ks][mt][1] = u32of(Ab[(r + 8) * AKP + kk]);
            af[ks][mt][2] = u32of(Ab[r * AKP + kk + 4]);
            af[ks][mt][3] = u32of(Ab[(r + 8) * AKP + kk + 4]);
        }
        #pragma unroll
        for (int nt = 0; nt < 8; nt++) {
            int cc = wn * 64 + nt * 8 + lr;
            if (BKN) {
                bf[ks][nt][0] = u32of(Bbuf[kk * BNP + cc]);
                bf[ks][nt][1] = u32of(Bbuf[(kk + 4) * BNP + cc]);
            } else {
                bf[ks][nt][0] = u32of(Bbuf[cc * AKP + kk]);
                bf[ks][nt][1] = u32of(Bbuf[cc * AKP + kk + 4]);
            }
        }
    }
    #pragma unroll
    for (int ks = 0; ks < 2; ks++)
        #pragma unroll
        for (int mt = 0; mt < 4; mt++)
            #pragma unroll
            for (int nt = 0; nt < 8; nt++)
                mma8(F.acc[mt][nt], af[ks][mt], bf[ks][nt]);
}

// ---------------------------------------------------------------------------
// Standard GEMM
// ---------------------------------------------------------------------------
template<bool AHID, int EPI, bool ROUND>
__global__ __launch_bounds__(NT, 2)
void gemm_tc(const float* __restrict__ A, const float* __restrict__ W,
             const float* __restrict__ bias, const float* __restrict__ R,
             float* __restrict__ C, float* __restrict__ C2, int K, int N, int CN)
{
    extern __shared__ float sm[];
    float* As = sm;
    float* Bs = sm + ST * BM * AKP;

    const int tid  = threadIdx.x;
    const int lane = tid & 31;
    const int warp = tid >> 5;
    const int wm   = warp & 1;
    const int wn   = warp >> 1;
    const int lr   = lane >> 2;
    const int lc   = lane & 3;
    const int m0   = blockIdx.y * BM;
    const int n0   = blockIdx.x * BN;
    const int KT   = K / BK;

    auto issue = [&](int kt) {
        int st = kt % ST;
        float* Ad = As + st * BM * AKP;
        float* Bd = Bs + st * BK * BNP;
        #pragma unroll
        for (int u = 0; u < 4; u++) {
            int c = tid + u * NT;
            int m = c >> 2, k4 = c & 3;
            const float* g = (AHID ? (A + hid_off(m0 + m)) : (A + (size_t)(m0 + m) * K))
                             + kt * BK + k4 * 4;
            cp16(Ad + m * AKP + k4 * 4, g);
        }
        #pragma unroll
        for (int u = 0; u < 4; u++) {
            int c = tid + u * NT;
            int k = c >> 5, n4 = c & 31;
            cp16(Bd + k * BNP + n4 * 4, W + (size_t)(kt * BK + k) * N + n0 + n4 * 4);
        }
        cp_commit();
    };

    Frag F; F.zero();

    #pragma unroll
    for (int p = 0; p < ST - 1; p++) issue(p);

    for (int kt = 0; kt < KT; ++kt) {
        cp_wait<ST - 2>();
        __syncthreads();
        tile_mma<true>(F, As + (kt % ST) * BM * AKP, Bs + (kt % ST) * BK * BNP,
                       wm, wn, lr, lc);
        if (kt + ST - 1 < KT) issue(kt + ST - 1); else cp_commit();
    }

    #pragma unroll
    for (int nt = 0; nt < 8; nt++) {
        int c = n0 + wn * 64 + nt * 8 + lc * 2;
        float bv0 = bias[c], bv1 = bias[c + 1];
        #pragma unroll
        for (int mt = 0; mt < 4; mt++) {
            int r0 = m0 + wm * 64 + mt * 16 + lr;
            int r1 = r0 + 8;
            float v00 = F.acc[mt][nt][0] + bv0;
            float v01 = F.acc[mt][nt][1] + bv1;
            float v10 = F.acc[mt][nt][2] + bv0;
            float v11 = F.acc[mt][nt][3] + bv1;
            if (EPI == E_GELU) {
                v00 = 0.5f * v00 * (1.f + erff(v00 * 0.70710678118654752f));
                v01 = 0.5f * v01 * (1.f + erff(v01 * 0.70710678118654752f));
                v10 = 0.5f * v10 * (1.f + erff(v10 * 0.70710678118654752f));
                v11 = 0.5f * v11 * (1.f + erff(v11 * 0.70710678118654752f));
            } else if (EPI == E_RES_HID) {
                const float* rp0 = R + hid_off(r0) + c;
                const float* rp1 = R + hid_off(r1) + c;
                v00 += rp0[0]; v01 += rp0[1];
                v10 += rp1[0]; v11 += rp1[1];
            } else if (EPI == E_RES_TRANS) {
                const float* rp0 = R + (size_t)r0 * CN + c;
                const float* rp1 = R + (size_t)r1 * CN + c;
                v00 += rp0[0]; v01 += rp0[1];
                v10 += rp1[0]; v11 += rp1[1];
            }
            if (EPI == E_RES_HID) {
                *reinterpret_cast<float2*>(C  + (size_t)r0 * CN + c) = make_float2(v00, v01);
                *reinterpret_cast<float2*>(C  + (size_t)r1 * CN + c) = make_float2(v10, v11);
                *reinterpret_cast<float2*>(C2 + (size_t)r0 * CN + c) =
                    make_float2(rnd_tf32(v00), rnd_tf32(v01));
                *reinterpret_cast<float2*>(C2 + (size_t)r1 * CN + c) =
                    make_float2(rnd_tf32(v10), rnd_tf32(v11));
            } else {
                if (ROUND) {
                    v00 = rnd_tf32(v00); v01 = rnd_tf32(v01);
                    v10 = rnd_tf32(v10); v11 = rnd_tf32(v11);
                }
                if (EPI == E_RES_TRANS) {
                    *reinterpret_cast<float2*>(C + hid_off(r0) + c) = make_float2(v00, v01);
                    *reinterpret_cast<float2*>(C + hid_off(r1) + c) = make_float2(v10, v11);
                } else {
                    *reinterpret_cast<float2*>(C + (size_t)r0 * CN + c) = make_float2(v00, v01);
                    *reinterpret_cast<float2*>(C + (size_t)r1 * CN + c) = make_float2(v10, v11);
                }
            }
        }
    }
}

// ---------------------------------------------------------------------------
// Scores with full-tile mask skipping.
// ---------------------------------------------------------------------------
__global__ __launch_bounds__(NT, 2)
void scores_tc(const float* __restrict__ qkv, const float* __restrict__ past_k,
               const int* __restrict__ past_lens, float* __restrict__ scores)
{
    extern __shared__ float sm[];
    float* As = sm;
    float* Bs = sm + ST * BM * AKP;

    const int tid  = threadIdx.x;
    const int lane = tid & 31;
    const int warp = tid >> 5;
    const int wm   = warp & 1;
    const int wn   = warp >> 1;
    const int lr   = lane >> 2;
    const int lc   = lane & 3;
    const int b    = blockIdx.z;
    const int m0   = blockIdx.y * BM;
    const int n0   = blockIdx.x * BN;
    const int KT   = Hh / BK;

    const int L = past_lens[b];

    // Fully-masked tile? (past tile beyond L, or causal tile fully below diagonal)
    bool dead = (n0 + BN <= Pp) ? (n0 >= L)
              : ((n0 >= Pp) && (n0 - Pp) > m0 + BM - 1);
    if (dead) {
        #pragma unroll
        for (int mt = 0; mt < 4; mt++) {
            #pragma unroll
            for (int nt = 0; nt < 8; nt++) {
                int c = n0 + wn * 64 + nt * 8 + lc * 2;
                #pragma unroll
                for (int half = 0; half < 2; half++) {
                    int s = m0 + wm * 64 + mt * 16 + lr + half * 8;
                    *reinterpret_cast<float2*>(scores + ((size_t)b * S_ + s) * Tt + c) =
                        make_float2(NEG_BIG, NEG_BIG);
                }
            }
        }
        return;
    }

    const float* Aq = qkv + (size_t)b * S_ * QKVN;

    auto keyrow = [&](int j) -> const float* {
        return (j < Pp) ? (past_k + ((size_t)b * Pp + j) * Hh)
                        : (qkv + ((size_t)b * S_ + (j - Pp)) * QKVN + Hh);
    };
    auto issue = [&](int kt) {
        int st = kt % ST;
        float* Ad = As + st * BM * AKP;
        float* Bd = Bs + st * BN * AKP;
        #pragma unroll
        for (int u = 0; u < 4; u++) {
            int c = tid + u * NT;
            int m = c >> 2, k4 = c & 3;
            cp16(Ad + m * AKP + k4 * 4, Aq + (size_t)(m0 + m) * QKVN + kt * BK + k4 * 4);
        }
        #pragma unroll
        for (int u = 0; u < 4; u++) {
            int c = tid + u * NT;
            int n = c >> 2, k4 = c & 3;
            cp16(Bd + n * AKP + k4 * 4, keyrow(n0 + n) + kt * BK + k4 * 4);
        }
        cp_commit();
    };

    Frag F; F.zero();

    #pragma unroll
    for (int p = 0; p < ST - 1; p++) issue(p);

    for (int kt = 0; kt < KT; ++kt) {
        cp_wait<ST - 2>();
        __syncthreads();
        tile_mma<false>(F, As + (kt % ST) * BM * AKP, Bs + (kt % ST) * BN * AKP,
                        wm, wn, lr, lc);
        if (kt + ST - 1 < KT) issue(kt + ST - 1); else cp_commit();
    }

    #pragma unroll
    for (int mt = 0; mt < 4; mt++) {
        #pragma unroll
        for (int nt = 0; nt < 8; nt++) {
            int c = n0 + wn * 64 + nt * 8 + lc * 2;
            #pragma unroll
            for (int half = 0; half < 2; half++) {
                int s = m0 + wm * 64 + mt * 16 + lr + half * 8;
                float v0 = F.acc[mt][nt][half * 2 + 0];
                float v1 = F.acc[mt][nt][half * 2 + 1];
                bool ok0 = (c < Pp) ? (c < L) : ((c - Pp) <= s);
                int c1 = c + 1;
                bool ok1 = (c1 < Pp) ? (c1 < L) : ((c1 - Pp) <= s);
                float o0 = ok0 ? v0 * SCALE : NEG_BIG;
                float o1 = ok1 ? v1 * SCALE : NEG_BIG;
                *reinterpret_cast<float2*>(scores + ((size_t)b * S_ + s) * Tt + c) =
                    make_float2(o0, o1);
            }
        }
    }
}

// ---------------------------------------------------------------------------
// PV with k-tile skipping (probs in masked regions are exactly 0).
// Valid k-tiles: past [0, ceil(L/16)) and new [128, 128 + m0/16 + 8).
// ---------------------------------------------------------------------------
__global__ __launch_bounds__(NT, 2)
void pv_tc(const float* __restrict__ probs, const float* __restrict__ past_v,
           const float* __restrict__ qkv, float* __restrict__ attn,
           const int* __restrict__ past_lens)
{
    extern __shared__ float sm[];
    float* As = sm;
    float* Bs = sm + ST * BM * AKP;

    const int tid  = threadIdx.x;
    const int lane = tid & 31;
    const int warp = tid >> 5;
    const int wm   = warp & 1;
    const int wn   = warp >> 1;
    const int lr   = lane >> 2;
    const int lc   = lane & 3;
    const int b    = blockIdx.z;
    const int m0   = blockIdx.y * BM;
    const int n0   = blockIdx.x * BN;

    const int L  = past_lens[b];
    const int ne = (L + 15) >> 4;              // valid past k-tiles
    const int nn = (m0 >> 4) + 8;              // valid new-seg k-tiles
    const int total = ne + nn;

    const float* Ap = probs + (size_t)b * S_ * Tt;

    auto kmap = [&](int i) { return (i < ne) ? i : 128 + (i - ne); };
    auto vrow = [&](int kidx) -> const float* {
        return (kidx < Pp) ? (past_v + ((size_t)b * Pp + kidx) * Hh)
                           : (qkv + ((size_t)b * S_ + (kidx - Pp)) * QKVN + 2 * Hh);
    };
    auto issue = [&](int i) {
        int kt = kmap(i);
        int st = i % ST;
        float* Ad = As + st * BM * AKP;
        float* Bd = Bs + st * BK * BNP;
        #pragma unroll
        for (int u = 0; u < 4; u++) {
            int c = tid + u * NT;
            int m = c >> 2, k4 = c & 3;
            cp16(Ad + m * AKP + k4 * 4, Ap + (size_t)(m0 + m) * Tt + kt * BK + k4 * 4);
        }
        #pragma unroll
        for (int u = 0; u < 4; u++) {
            int c = tid + u * NT;
            int k = c >> 5, n4 = c & 31;
            cp16(Bd + k * BNP + n4 * 4, vrow(kt * BK + k) + n0 + n4 * 4);
        }
        cp_commit();
    };

    Frag F; F.zero();

    #pragma unroll
    for (int p = 0; p < ST - 1; p++) if (p < total) issue(p);

    for (int i = 0; i < total; ++i) {
        cp_wait<ST - 2>();
        __syncthreads();
        tile_mma<true>(F, As + (i % ST) * BM * AKP, Bs + (i % ST) * BK * BNP,
                       wm, wn, lr, lc);
        if (i + ST - 1 < total) issue(i + ST - 1); else cp_commit();
    }

    #pragma unroll
    for (int mt = 0; mt < 4; mt++) {
        #pragma unroll
        for (int nt = 0; nt < 8; nt++) {
            int c = n0 + wn * 64 + nt * 8 + lc * 2;
            int r0 = m0 + wm * 64 + mt * 16 + lr;
            int r1 = r0 + 8;
            *reinterpret_cast<float2*>(attn + ((size_t)b * S_ + r0) * Hh + c) =
                make_float2(rnd_tf32(F.acc[mt][nt][0]), rnd_tf32(F.acc[mt][nt][1]));
            *reinterpret_cast<float2*>(attn + ((size_t)b * S_ + r1) * Hh + c) =
                make_float2(rnd_tf32(F.acc[mt][nt][2]), rnd_tf32(F.acc[mt][nt][3]));
        }
    }
}

// ---------------------------------------------------------------------------
// Row softmax
// ---------------------------------------------------------------------------
__global__ __launch_bounds__(256)
void softmax_kernel(float* __restrict__ scores)
{
    __shared__ float red[8];
    const int tid = threadIdx.x;
    float* p = scores + (size_t)blockIdx.x * Tt;

    float v[9];
    float mx = NEG_BIG;
    #pragma unroll
    for (int i = 0; i < 9; i++) { v[i] = p[tid + (i << 8)]; mx = fmaxf(mx, v[i]); }
    #pragma unroll
    for (int o = 16; o > 0; o >>= 1) mx = fmaxf(mx, __shfl_xor_sync(0xffffffffu, mx, o));
    if ((tid & 31) == 0) red[tid >> 5] = mx;
    __syncthreads();
    float m2 = red[0];
    #pragma unroll
    for (int i = 1; i < 8; i++) m2 = fmaxf(m2, red[i]);

    float sum = 0.f;
    #pragma unroll
    for (int i = 0; i < 9; i++) { v[i] = __expf(v[i] - m2); sum += v[i]; }
    #pragma unroll
    for (int o = 16; o > 0; o >>= 1) sum += __shfl_xor_sync(0xffffffffu, sum, o);
    __syncthreads();
    if ((tid & 31) == 0) red[tid >> 5] = sum;
    __syncthreads();
    float s2 = 0.f;
    #pragma unroll
    for (int i = 0; i < 8; i++) s2 += red[i];

    float inv = 1.f / s2;
    #pragma unroll
    for (int i = 0; i < 9; i++) p[tid + (i << 8)] = rnd_tf32(v[i] * inv);
}

// ---------------------------------------------------------------------------
// Launch
// ---------------------------------------------------------------------------
extern "C" void kernel_launch(void* const* d_in, const int* in_sizes, int n_in,
                              void* d_out, int out_size)
{
    const float* hidden    = (const float*)d_in[0];
    const float* past_k    = (const float*)d_in[1];
    const float* past_v    = (const float*)d_in[2];
    const int*   past_lens = (const int*)  d_in[3];
    const float* Wq = (const float*)d_in[4];  const float* bq = (const float*)d_in[5];
    const float* Wk = (const float*)d_in[6];  const float* bk = (const float*)d_in[7];
    const float* Wv = (const float*)d_in[8];  const float* bv = (const float*)d_in[9];
    const float* Wo = (const float*)d_in[10]; const float* bo = (const float*)d_in[11];
    const float* W1 = (const float*)d_in[12]; const float* b1 = (const float*)d_in[13];
    const float* W2 = (const float*)d_in[14]; const float* b2 = (const float*)d_in[15];
    float* out = (float*)d_out;

    float *qkv, *sc, *at, *h1, *h1r, *act, *hr, *wqkv, *bqkv, *wo, *w1, *w2;
    cudaGetSymbolAddress((void**)&qkv,  g_qkv);
    cudaGetSymbolAddress((void**)&sc,   g_sc);
    cudaGetSymbolAddress((void**)&at,   g_at);
    cudaGetSymbolAddress((void**)&h1,   g_h1);
    cudaGetSymbolAddress((void**)&h1r,  g_h1r);
    cudaGetSymbolAddress((void**)&act,  g_act);
    cudaGetSymbolAddress((void**)&hr,   g_hr);
    cudaGetSymbolAddress((void**)&wqkv, g_wqkv);
    cudaGetSymbolAddress((void**)&bqkv, g_bqkv);
    cudaGetSymbolAddress((void**)&wo,   g_wo);
    cudaGetSymbolAddress((void**)&w1,   g_w1);
    cudaGetSymbolAddress((void**)&w2,   g_w2);

    cudaFuncSetAttribute(gemm_tc<true,  E_BIAS,      true >, cudaFuncAttributeMaxDynamicSharedMemorySize, SMEM_GEMM);
    cudaFuncSetAttribute(gemm_tc<false, E_RES_HID,   false>, cudaFuncAttributeMaxDynamicSharedMemorySize, SMEM_GEMM);
    cudaFuncSetAttribute(gemm_tc<false, E_GELU,      true >, cudaFuncAttributeMaxDynamicSharedMemorySize, SMEM_GEMM);
    cudaFuncSetAttribute(gemm_tc<false, E_RES_TRANS, false>, cudaFuncAttributeMaxDynamicSharedMemorySize, SMEM_GEMM);
    cudaFuncSetAttribute(scores_tc, cudaFuncAttributeMaxDynamicSharedMemorySize, SMEM_SCORES);
    cudaFuncSetAttribute(pv_tc,     cudaFuncAttributeMaxDynamicSharedMemorySize, SMEM_GEMM);

    prep_kernel<<<(F4_TOTAL + 255) / 256, 256>>>(hidden, Wq, Wk, Wv, Wo, W1, W2, bq, bk, bv);

    dim3 blk(NT);

    gemm_tc<true, E_BIAS, true><<<dim3(QKVN / BN, Mm / BM), blk, SMEM_GEMM>>>(
        hr, wqkv, bqkv, nullptr, qkv, nullptr, Hh, QKVN, QKVN);

    scores_tc<<<dim3(Tt / BN, S_ / BM, Bb), blk, SMEM_SCORES>>>(qkv, past_k, past_lens, sc);
    softmax_kernel<<<Mm, 256>>>(sc);
    pv_tc<<<dim3(Hh / BN, S_ / BM, Bb), blk, SMEM_GEMM>>>(sc, past_v, qkv, at, past_lens);

    gemm_tc<false, E_RES_HID, false><<<dim3(Hh / BN, Mm / BM), blk, SMEM_GEMM>>>(
        at, wo, bo, hidden, h1, h1r, Hh, Hh, Hh);

    gemm_tc<false, E_GELU, true><<<dim3(Ff / BN, Mm / BM), blk, SMEM_GEMM>>>(
        h1r, w1, b1, nullptr, act, nullptr, Hh, Ff, Ff);
    gemm_tc<false, E_RES_TRANS, false><<<dim3(Hh / BN, Mm / BM), blk, SMEM_GEMM>>>(
        act, w2, b2, h1, out, nullptr, Ff, Hh, Hh);
}